// round 8
// baseline (speedup 1.0000x reference)
#include <cuda_runtime.h>
#include <cuda_bf16.h>
#include <math.h>
#include <stdint.h>

#define DD   768
#define NH   12
#define HDIM 64
#define SEQ  2048
#define BAT  4
#define NROWS (BAT*SEQ)   // 8192

typedef __nv_bfloat16 bf16;

// ---------------------------------------------------------------------------
// Scratch (static __device__ arrays — no allocation allowed)
// ---------------------------------------------------------------------------
__device__ bf16 g_hhi[NROWS*DD], g_hlo[NROWS*DD];
__device__ bf16 g_Wqhi[DD*DD], g_Wqlo[DD*DD];
__device__ bf16 g_Wkhi[DD*DD], g_Wklo[DD*DD];
__device__ bf16 g_Wvhi[DD*DD], g_Wvlo[DD*DD];
__device__ bf16 g_Wohi[DD*DD], g_Wolo[DD*DD];
__device__ bf16 g_Qhi[NROWS*DD], g_Qlo[NROWS*DD];   // [b,h,s,d]
__device__ bf16 g_Khi[NROWS*DD], g_Klo[NROWS*DD];   // [b,h,s,d]
__device__ bf16 g_Vhi[NROWS*DD], g_Vlo[NROWS*DD];   // [b,h,s,d]
__device__ bf16 g_Chi[NROWS*DD], g_Clo[NROWS*DD];   // [b*s, d_model]
__device__ float g_h[NROWS*DD];                     // pre-LN fp32

// ---------------------------------------------------------------------------
// PTX helpers (sm_80-compatible: mma.sync / ldmatrix / cp.async)
// ---------------------------------------------------------------------------
__device__ __forceinline__ uint32_t smem_to_u32(const void* p) {
    uint32_t a;
    asm("{ .reg .u64 t; cvta.to.shared.u64 t, %1; cvt.u32.u64 %0, t; }" : "=r"(a) : "l"(p));
    return a;
}
#define SWZ(o) ((uint32_t)(o) ^ ((((uint32_t)(o)) >> 3) & 0x70))

__device__ __forceinline__ void cp_async16(uint32_t s, const void* g) {
    asm volatile("cp.async.cg.shared.global [%0], [%1], 16;" :: "r"(s), "l"(g) : "memory");
}
__device__ __forceinline__ void cp_commit() {
    asm volatile("cp.async.commit_group;" ::: "memory");
}
template<int N>
__device__ __forceinline__ void cp_wait() {
    asm volatile("cp.async.wait_group %0;" :: "n"(N) : "memory");
}

__device__ __forceinline__ void ldsm_x4(uint32_t* r, uint32_t a) {
    asm volatile("ldmatrix.sync.aligned.m8n8.x4.shared.b16 {%0,%1,%2,%3}, [%4];"
        : "=r"(r[0]), "=r"(r[1]), "=r"(r[2]), "=r"(r[3]) : "r"(a));
}
__device__ __forceinline__ void ldsm_x4_t(uint32_t* r, uint32_t a) {
    asm volatile("ldmatrix.sync.aligned.m8n8.x4.trans.shared.b16 {%0,%1,%2,%3}, [%4];"
        : "=r"(r[0]), "=r"(r[1]), "=r"(r[2]), "=r"(r[3]) : "r"(a));
}

// D += A * B, m16n8k16 bf16 -> fp32
__device__ __forceinline__ void mma_bf(float* d, const uint32_t* a, const uint32_t* b) {
    asm volatile("mma.sync.aligned.m16n8k16.row.col.f32.bf16.bf16.f32 "
        "{%0,%1,%2,%3}, {%4,%5,%6,%7}, {%8,%9}, {%0,%1,%2,%3};"
        : "+f"(d[0]), "+f"(d[1]), "+f"(d[2]), "+f"(d[3])
        : "r"(a[0]), "r"(a[1]), "r"(a[2]), "r"(a[3]), "r"(b[0]), "r"(b[1]));
}

// Fast hi/lo split of 2 fp32 (cvt.rn.bf16x2 + bit tricks)
__device__ __forceinline__ void split2(float v0, float v1, uint32_t& hi, uint32_t& lo) {
    uint32_t H;
    asm("cvt.rn.bf16x2.f32 %0, %1, %2;" : "=r"(H) : "f"(v1), "f"(v0));
    float h0 = __uint_as_float(H << 16);
    float h1 = __uint_as_float(H & 0xFFFF0000u);
    float l0 = v0 - h0, l1 = v1 - h1;
    uint32_t L;
    asm("cvt.rn.bf16x2.f32 %0, %1, %2;" : "=r"(L) : "f"(l1), "f"(l0));
    hi = H; lo = L;
}

// ---------------------------------------------------------------------------
// fp32 -> bf16 hi/lo split kernels
// ---------------------------------------------------------------------------
__global__ __launch_bounds__(256)
void split_kernel(const float4* __restrict__ x, uint32_t* __restrict__ hi2,
                  uint32_t* __restrict__ lo2, int n4)
{
    int i = blockIdx.x * 256 + threadIdx.x;
    if (i >= n4) return;
    float4 v = x[i];
    uint32_t h0, l0, h1, l1;
    split2(v.x, v.y, h0, l0);
    split2(v.z, v.w, h1, l1);
    uint2 H = make_uint2(h0, h1), L = make_uint2(l0, l1);
    *(uint2*)(hi2 + 2*i) = H;
    *(uint2*)(lo2 + 2*i) = L;
}

__global__ __launch_bounds__(256)
void split_w4(const float4* __restrict__ w0, const float4* __restrict__ w1,
              const float4* __restrict__ w2, const float4* __restrict__ w3,
              uint32_t* __restrict__ h0, uint32_t* __restrict__ l0,
              uint32_t* __restrict__ h1, uint32_t* __restrict__ l1,
              uint32_t* __restrict__ h2, uint32_t* __restrict__ l2,
              uint32_t* __restrict__ h3, uint32_t* __restrict__ l3)
{
    const int n4 = DD * DD / 4;
    int i = blockIdx.x * 256 + threadIdx.x;
    if (i >= n4) return;
    int wsel = blockIdx.y;
    const float4* w = wsel == 0 ? w0 : (wsel == 1 ? w1 : (wsel == 2 ? w2 : w3));
    uint32_t* hh = wsel == 0 ? h0 : (wsel == 1 ? h1 : (wsel == 2 ? h2 : h3));
    uint32_t* ll = wsel == 0 ? l0 : (wsel == 1 ? l1 : (wsel == 2 ? l2 : l3));
    float4 v = w[i];
    uint32_t a0, b0, a1, b1;
    split2(v.x, v.y, a0, b0);
    split2(v.z, v.w, a1, b1);
    uint2 H = make_uint2(a0, a1), L = make_uint2(b0, b1);
    *(uint2*)(hh + 2*i) = H;
    *(uint2*)(ll + 2*i) = L;
}

// ---------------------------------------------------------------------------
// 3xBF16 HMMA GEMM (QKV fused): C[m,o] = sum_k A[m,k]*W[o,k] + bias[o]
// CTA 128x128, 256 thr (8 warps, 2x4), k-chunk 32, triple-buffered cp.async.
// ---------------------------------------------------------------------------
__global__ __launch_bounds__(256, 2)
void gemm_qkv(const bf16* __restrict__ Ahi, const bf16* __restrict__ Alo,
              const bf16* __restrict__ W0h, const bf16* __restrict__ W0l, const float* __restrict__ b0,
              const bf16* __restrict__ W1h, const bf16* __restrict__ W1l, const float* __restrict__ b1,
              const bf16* __restrict__ W2h, const bf16* __restrict__ W2l, const float* __restrict__ b2,
              bf16* __restrict__ O0h, bf16* __restrict__ O0l,
              bf16* __restrict__ O1h, bf16* __restrict__ O1l,
              bf16* __restrict__ O2h, bf16* __restrict__ O2l)
{
    extern __shared__ char smem[];
    const uint32_t sb = smem_to_u32(smem);
    const int t = threadIdx.x, lane = t & 31, wid = t >> 5;
    const int wm = wid >> 2, wn = wid & 3;
    const int nbase = blockIdx.x * 128, obase = blockIdx.y * 128;
    const int which = blockIdx.z;
    const bf16*  Bh   = which == 0 ? W0h : (which == 1 ? W1h : W2h);
    const bf16*  Bl   = which == 0 ? W0l : (which == 1 ? W1l : W2l);
    const float* bias = which == 0 ? b0  : (which == 1 ? b1  : b2);
    bf16* Oh = which == 0 ? O0h : (which == 1 ? O1h : O2h);
    bf16* Ol = which == 0 ? O0l : (which == 1 ? O1l : O2l);

    float acc[4][4][4];
    #pragma unroll
    for (int i = 0; i < 4; i++)
        #pragma unroll
        for (int j = 0; j < 4; j++)
            #pragma unroll
            for (int k = 0; k < 4; k++) acc[i][j][k] = 0.0f;

    auto prefetch = [&](int ic, int st) {
        #pragma unroll
        for (int q = 0; q < 8; q++) {
            int idx = t + 256 * q;
            int rg  = idx >> 10;            // 0=A, 1=B
            int row = (idx >> 3) & 127;
            int c16 = idx & 7;              // 0..3 hi, 4..7 lo
            uint32_t so = sb + st * 32768u + (rg ? 16384u : 0u) + SWZ(row * 128 + c16 * 16);
            const bf16* gp = rg == 0
                ? ((c16 < 4 ? Ahi : Alo) + (size_t)(nbase + row) * DD + ic * 32 + (c16 & 3) * 8)
                : ((c16 < 4 ? Bh  : Bl ) + (size_t)(obase + row) * DD + ic * 32 + (c16 & 3) * 8);
            cp_async16(so, gp);
        }
        cp_commit();
    };

    prefetch(0, 0);
    prefetch(1, 1);
    for (int ic = 0; ic < 24; ic++) {
        if (ic < 23) cp_wait<1>(); else cp_wait<0>();
        __syncthreads();
        if (ic + 2 < 24) prefetch(ic + 2, (ic + 2) % 3);

        const uint32_t sA = sb + (ic % 3) * 32768u;
        const uint32_t sB = sA + 16384u;
        #pragma unroll
        for (int k16 = 0; k16 < 2; k16++) {
            uint32_t ah[4][4], al[4][4];
            #pragma unroll
            for (int mt = 0; mt < 4; mt++) {
                int row = wm * 64 + mt * 16 + (lane & 15);
                int ch  = k16 * 2 + (lane >> 4);
                ldsm_x4(ah[mt], sA + SWZ(row * 128 + ch * 16));
                ldsm_x4(al[mt], sA + SWZ(row * 128 + (ch + 4) * 16));
            }
            #pragma unroll
            for (int ntp = 0; ntp < 2; ntp++) {
                uint32_t bh4[4], bl4[4];
                int row = wn * 32 + (ntp * 2 + (lane >> 4)) * 8 + (lane & 7);
                int ch  = k16 * 2 + ((lane >> 3) & 1);
                ldsm_x4(bh4, sB + SWZ(row * 128 + ch * 16));
                ldsm_x4(bl4, sB + SWZ(row * 128 + (ch + 4) * 16));
                #pragma unroll
                for (int mt = 0; mt < 4; mt++) {
                    mma_bf(acc[mt][2*ntp],   ah[mt], bh4 + 0);
                    mma_bf(acc[mt][2*ntp],   ah[mt], bl4 + 0);
                    mma_bf(acc[mt][2*ntp],   al[mt], bh4 + 0);
                    mma_bf(acc[mt][2*ntp+1], ah[mt], bh4 + 2);
                    mma_bf(acc[mt][2*ntp+1], ah[mt], bl4 + 2);
                    mma_bf(acc[mt][2*ntp+1], al[mt], bh4 + 2);
                }
            }
        }
    }

    // Epilogue: + bias, split hi/lo, scatter to [b,h,s,d]
    #pragma unroll
    for (int nt = 0; nt < 4; nt++) {
        const int col = obase + wn * 32 + nt * 8 + 2 * (lane & 3);
        const float2 bs = *(const float2*)(bias + col);
        const int hh = col >> 6, dd = col & 63;
        #pragma unroll
        for (int mt = 0; mt < 4; mt++) {
            const int r0 = nbase + wm * 64 + mt * 16 + (lane >> 2);
            #pragma unroll
            for (int half = 0; half < 2; half++) {
                const int r = r0 + half * 8;
                const int bb = r >> 11, ss = r & 2047;
                const size_t idx = (((size_t)(bb * NH + hh) * SEQ) + ss) * HDIM + dd;
                uint32_t H, L;
                split2(acc[mt][nt][2*half] + bs.x, acc[mt][nt][2*half+1] + bs.y, H, L);
                *(uint32_t*)(Oh + idx) = H;
                *(uint32_t*)(Ol + idx) = L;
            }
        }
    }
}

// ---------------------------------------------------------------------------
// 3xBF16 HMMA GEMM (O-proj): out fp32 = C·Wo^T + bias + residual
// 64x128 CTA tile, 256 thr, k-chunk 32, triple-buffered. Stage = 24KB.
// ---------------------------------------------------------------------------
__global__ __launch_bounds__(256, 2)
void gemm_o(const bf16* __restrict__ Ahi, const bf16* __restrict__ Alo,
            const bf16* __restrict__ Bh, const bf16* __restrict__ Bl,
            const float* __restrict__ bias, const float* __restrict__ res,
            float* __restrict__ Of)
{
    extern __shared__ char smem[];
    const uint32_t sb = smem_to_u32(smem);
    const int t = threadIdx.x, lane = t & 31, wid = t >> 5;
    const int wm = wid >> 2, wn = wid & 3;     // wm 0..1 (m32), wn 0..3 (n32)
    const int nbase = blockIdx.x * 64, obase = blockIdx.y * 128;

    float acc[2][4][4];
    #pragma unroll
    for (int i = 0; i < 2; i++)
        #pragma unroll
        for (int j = 0; j < 4; j++)
            #pragma unroll
            for (int k = 0; k < 4; k++) acc[i][j][k] = 0.0f;

    auto prefetch = [&](int ic, int st) {
        #pragma unroll
        for (int q = 0; q < 6; q++) {
            int idx = t + 256 * q;             // 0..1535
            uint32_t stage = sb + st * 24576u;
            if (idx < 512) {                   // A: 64 rows x 8 c16
                int row = idx >> 3, c16 = idx & 7;
                const bf16* gp = (c16 < 4 ? Ahi : Alo)
                    + (size_t)(nbase + row) * DD + ic * 32 + (c16 & 3) * 8;
                cp_async16(stage + SWZ(row * 128 + c16 * 16), gp);
            } else {                            // B: 128 rows x 8 c16
                int j = idx - 512;
                int row = j >> 3, c16 = j & 7;
                const bf16* gp = (c16 < 4 ? Bh : Bl)
                    + (size_t)(obase + row) * DD + ic * 32 + (c16 & 3) * 8;
                cp_async16(stage + 8192u + SWZ(row * 128 + c16 * 16), gp);
            }
        }
        cp_commit();
    };

    prefetch(0, 0);
    prefetch(1, 1);
    for (int ic = 0; ic < 24; ic++) {
        if (ic < 23) cp_wait<1>(); else cp_wait<0>();
        __syncthreads();
        if (ic + 2 < 24) prefetch(ic + 2, (ic + 2) % 3);

        const uint32_t sA = sb + (ic % 3) * 24576u;
        const uint32_t sB = sA + 8192u;
        #pragma unroll
        for (int k16 = 0; k16 < 2; k16++) {
            uint32_t ah[2][4], al[2][4];
            #pragma unroll
            for (int mt = 0; mt < 2; mt++) {
                int row = wm * 32 + mt * 16 + (lane & 15);
                int ch  = k16 * 2 + (lane >> 4);
                ldsm_x4(ah[mt], sA + SWZ(row * 128 + ch * 16));
                ldsm_x4(al[mt], sA + SWZ(row * 128 + (ch + 4) * 16));
            }
            #pragma unroll
            for (int ntp = 0; ntp < 2; ntp++) {
                uint32_t bh4[4], bl4[4];
                int row = wn * 32 + (ntp * 2 + (lane >> 4)) * 8 + (lane & 7);
                int ch  = k16 * 2 + ((lane >> 3) & 1);
                ldsm_x4(bh4, sB + SWZ(row * 128 + ch * 16));
                ldsm_x4(bl4, sB + SWZ(row * 128 + (ch + 4) * 16));
                #pragma unroll
                for (int mt = 0; mt < 2; mt++) {
                    mma_bf(acc[mt][2*ntp],   ah[mt], bh4 + 0);
                    mma_bf(acc[mt][2*ntp],   ah[mt], bl4 + 0);
                    mma_bf(acc[mt][2*ntp],   al[mt], bh4 + 0);
                    mma_bf(acc[mt][2*ntp+1], ah[mt], bh4 + 2);
                    mma_bf(acc[mt][2*ntp+1], ah[mt], bl4 + 2);
                    mma_bf(acc[mt][2*ntp+1], al[mt], bh4 + 2);
                }
            }
        }
    }

    #pragma unroll
    for (int nt = 0; nt < 4; nt++) {
        const int col = obase + wn * 32 + nt * 8 + 2 * (lane & 3);
        const float2 bs = *(const float2*)(bias + col);
        #pragma unroll
        for (int mt = 0; mt < 2; mt++) {
            const int r0 = nbase + wm * 32 + mt * 16 + (lane >> 2);
            #pragma unroll
            for (int half = 0; half < 2; half++) {
                const int r = r0 + half * 8;
                const size_t idx = (size_t)r * DD + col;
                const float2 rr = *(const float2*)(res + idx);
                float2 o;
                o.x = acc[mt][nt][2*half]   + bs.x + rr.x;
                o.y = acc[mt][nt][2*half+1] + bs.y + rr.y;
                *(float2*)(Of + idx) = o;
            }
        }
    }
}

// ---------------------------------------------------------------------------
// Flash attention, 3xBF16 HMMA, no-max softmax, O accumulates in registers.
// CTA = 128 q-rows, 128 thr (4 warps x 32 q-rows = 2 m16 frags per warp):
// K/V ldsm per warp amortizes over 2x the HMMA -> smem pressure halved.
// 64KB smem = 4 x 16KB KV ring; Q hi/lo parked in stages 2,3 and reused
// after fragment extraction. 32-key tiles, distance-2 prefetch, 1 sync/tile.
// 2 CTAs/SM (256-reg budget).
// ---------------------------------------------------------------------------
__global__ __launch_bounds__(128, 2)
void attn_mma(const bf16* __restrict__ Qhi, const bf16* __restrict__ Qlo,
              const bf16* __restrict__ Khi, const bf16* __restrict__ Klo,
              const bf16* __restrict__ Vhi, const bf16* __restrict__ Vlo,
              bf16* __restrict__ Chi, bf16* __restrict__ Clo)
{
    extern __shared__ char smem[];
    const uint32_t sb = smem_to_u32(smem);
    const int t = threadIdx.x, lane = t & 31, wid = t >> 5;
    const int bh = blockIdx.y, q0 = blockIdx.x * 128;
    const size_t bhoff = (size_t)bh * SEQ * HDIM;

    // Q tile (128 rows, hi+lo = 32KB) -> stages 2,3 (sb+32KB hi, sb+48KB lo)
    #pragma unroll
    for (int q = 0; q < 16; q++) {
        int idx = t + 128 * q;                 // 0..2047
        int rg = idx >> 10;                    // 0 hi, 1 lo
        int row = (idx >> 3) & 127;
        int c16 = idx & 7;
        uint32_t so = sb + 32768u + rg * 16384u + SWZ(row * 128 + c16 * 16);
        const bf16* gp = (rg ? Qlo : Qhi) + bhoff + (size_t)(q0 + row) * HDIM + c16 * 8;
        cp_async16(so, gp);
    }
    cp_commit();

    // KV stage (32 keys): KH 4KB | KL 4KB | VH 4KB | VL 4KB = 16KB at st*16KB
    auto prefetch_kv = [&](int kt, int st) {
        #pragma unroll
        for (int q = 0; q < 8; q++) {
            int idx = t + 128 * q;             // 0..1023
            int rg  = idx >> 8;                // 0 KH, 1 KL, 2 VH, 3 VL
            int row = (idx >> 3) & 31;
            int c16 = idx & 7;
            uint32_t so = sb + st * 16384u + rg * 4096u + SWZ(row * 128 + c16 * 16);
            const bf16* base = rg == 0 ? Khi : (rg == 1 ? Klo : (rg == 2 ? Vhi : Vlo));
            cp_async16(so, base + bhoff + (size_t)(kt * 32 + row) * HDIM + c16 * 8);
        }
        cp_commit();
    };

    prefetch_kv(0, 0);
    prefetch_kv(1, 1);
    cp_wait<1>();        // Q + kv0 done (kv1 in flight)
    __syncthreads();

    // Q fragments (persistent): 2 m-frags per warp (rows wid*32 + m*16 + ...)
    uint32_t qh[2][4][4], ql[2][4][4];
    #pragma unroll
    for (int m = 0; m < 2; m++)
        #pragma unroll
        for (int k16 = 0; k16 < 4; k16++) {
            int row = wid * 32 + m * 16 + (lane & 15);
            int ch  = k16 * 2 + (lane >> 4);
            ldsm_x4(qh[m][k16], sb + 32768u + SWZ(row * 128 + ch * 16));
            ldsm_x4(ql[m][k16], sb + 49152u + SWZ(row * 128 + ch * 16));
        }
    __syncthreads();     // Q fully extracted before stages 2,3 are reused

    float oacc[2][8][4];
    #pragma unroll
    for (int m = 0; m < 2; m++)
        #pragma unroll
        for (int i = 0; i < 8; i++)
            #pragma unroll
            for (int j = 0; j < 4; j++) oacc[m][i][j] = 0.0f;
    float lsum[2][2] = {{0.f, 0.f}, {0.f, 0.f}};

    for (int kt = 0; kt < 64; kt++) {
        if (kt > 0) {
            if (kt < 63) cp_wait<1>(); else cp_wait<0>();
            __syncthreads();   // stage kt ready; stage (kt+2)&3 fully consumed
        }
        if (kt + 2 < 64) prefetch_kv(kt + 2, (kt + 2) & 3);

        const uint32_t sKH = sb + (uint32_t)(kt & 3) * 16384u;
        const uint32_t sKL = sKH + 4096u;
        const uint32_t sVH = sKH + 8192u;
        const uint32_t sVL = sKH + 12288u;

        // S = Q·K^T over 32 keys, 2 m-frags (K-frags shared across m)
        float sacc[2][4][4];
        #pragma unroll
        for (int m = 0; m < 2; m++)
            #pragma unroll
            for (int i = 0; i < 4; i++)
                #pragma unroll
                for (int j = 0; j < 4; j++) sacc[m][i][j] = 0.0f;

        #pragma unroll
        for (int ntp = 0; ntp < 2; ntp++) {
            #pragma unroll
            for (int k16 = 0; k16 < 4; k16++) {
                uint32_t kh4[4], kl4[4];
                int row = (ntp * 2 + (lane >> 4)) * 8 + (lane & 7);
                int ch  = k16 * 2 + ((lane >> 3) & 1);
                ldsm_x4(kh4, sKH + SWZ(row * 128 + ch * 16));
                ldsm_x4(kl4, sKL + SWZ(row * 128 + ch * 16));
                #pragma unroll
                for (int m = 0; m < 2; m++) {
                    mma_bf(sacc[m][2*ntp],   qh[m][k16], kh4 + 0);
                    mma_bf(sacc[m][2*ntp+1], qh[m][k16], kh4 + 2);
                    mma_bf(sacc[m][2*ntp],   qh[m][k16], kl4 + 0);
                    mma_bf(sacc[m][2*ntp+1], qh[m][k16], kl4 + 2);
                    mma_bf(sacc[m][2*ntp],   ql[m][k16], kh4 + 0);
                    mma_bf(sacc[m][2*ntp+1], ql[m][k16], kh4 + 2);
                }
            }
        }

        // exp (no shift) + pack P as A-fragments (hi/lo), per m-frag
        uint32_t ph[2][2][4], pl[2][2][4];
        #pragma unroll
        for (int m = 0; m < 2; m++)
            #pragma unroll
            for (int pp = 0; pp < 2; pp++) {
                float e[8];
                #pragma unroll
                for (int j = 0; j < 4; j++) {
                    e[j]     = __expf(sacc[m][2*pp][j]);
                    e[4 + j] = __expf(sacc[m][2*pp+1][j]);
                }
                lsum[m][0] += (e[0] + e[1]) + (e[4] + e[5]);
                lsum[m][1] += (e[2] + e[3]) + (e[6] + e[7]);
                split2(e[0], e[1], ph[m][pp][0], pl[m][pp][0]);
                split2(e[2], e[3], ph[m][pp][1], pl[m][pp][1]);
                split2(e[4], e[5], ph[m][pp][2], pl[m][pp][2]);
                split2(e[6], e[7], ph[m][pp][3], pl[m][pp][3]);
            }

        // O += P·V (V-frags shared across m)
        #pragma unroll
        for (int pp = 0; pp < 2; pp++) {
            const int kk0 = pp * 16;
            #pragma unroll
            for (int dtp = 0; dtp < 4; dtp++) {
                uint32_t vh4[4], vl4[4];
                int row = kk0 + (lane & 15);
                int ch  = dtp * 2 + (lane >> 4);
                ldsm_x4_t(vh4, sVH + SWZ(row * 128 + ch * 16));
                ldsm_x4_t(vl4, sVL + SWZ(row * 128 + ch * 16));
                #pragma unroll
                for (int m = 0; m < 2; m++) {
                    mma_bf(oacc[m][2*dtp],   ph[m][pp], vh4 + 0);
                    mma_bf(oacc[m][2*dtp+1], ph[m][pp], vh4 + 2);
                    mma_bf(oacc[m][2*dtp],   ph[m][pp], vl4 + 0);
                    mma_bf(oacc[m][2*dtp+1], ph[m][pp], vl4 + 2);
                    mma_bf(oacc[m][2*dtp],   pl[m][pp], vh4 + 0);
                    mma_bf(oacc[m][2*dtp+1], pl[m][pp], vh4 + 2);
                }
            }
        }
    }

    // Row sums across the quad, then normalize + store (per m-frag)
    const int bb = bh / NH, hh = bh % NH;
    #pragma unroll
    for (int m = 0; m < 2; m++) {
        float l0 = lsum[m][0], l1 = lsum[m][1];
        l0 += __shfl_xor_sync(0xffffffffu, l0, 1);
        l0 += __shfl_xor_sync(0xffffffffu, l0, 2);
        l1 += __shfl_xor_sync(0xffffffffu, l1, 1);
        l1 += __shfl_xor_sync(0xffffffffu, l1, 2);
        const float inv0 = 1.0f / l0, inv1 = 1.0f / l1;
        const int r0 = q0 + wid * 32 + m * 16 + (lane >> 2);
        #pragma unroll
        for (int dt = 0; dt < 8; dt++) {
            const int col = hh * 64 + dt * 8 + 2 * (lane & 3);
            const size_t i0 = ((size_t)(bb * SEQ) + r0) * DD + col;
            const size_t i1 = i0 + (size_t)8 * DD;
            uint32_t H, L;
            split2(oacc[m][dt][0] * inv0, oacc[m][dt][1] * inv0, H, L);
            *(uint32_t*)(Chi + i0) = H; *(uint32_t*)(Clo + i0) = L;
            split2(oacc[m][dt][2] * inv1, oacc[m][dt][3] * inv1, H, L);
            *(uint32_t*)(Chi + i1) = H; *(uint32_t*)(Clo + i1) = L;
        }
    }
}

// ---------------------------------------------------------------------------
// LayerNorm (custom): mean, unbiased std (ddof=1), (x-mean)/(std+eps)
// ---------------------------------------------------------------------------
__global__ __launch_bounds__(192)
void ln_kernel(const float* __restrict__ Hin, float* __restrict__ out)
{
    __shared__ float red[6];
    const int rowb = blockIdx.x;
    const int t = threadIdx.x;
    const float4 v = *(const float4*)(Hin + (size_t)rowb * DD + t * 4);

    float s = (v.x + v.y) + (v.z + v.w);
    #pragma unroll
    for (int off = 16; off >= 1; off >>= 1) s += __shfl_xor_sync(0xffffffffu, s, off);
    if ((t & 31) == 0) red[t >> 5] = s;
    __syncthreads();
    float tot = (red[0] + red[1]) + (red[2] + red[3]) + (red[4] + red[5]);
    const float mean = tot * (1.0f / 768.0f);

    float d0 = v.x - mean, d1 = v.y - mean, d2 = v.z - mean, d3 = v.w - mean;
    float sq = (d0 * d0 + d1 * d1) + (d2 * d2 + d3 * d3);
    #pragma unroll
    for (int off = 16; off >= 1; off >>= 1) sq += __shfl_xor_sync(0xffffffffu, sq, off);
    __syncthreads();
    if ((t & 31) == 0) red[t >> 5] = sq;
    __syncthreads();
    float ssq = (red[0] + red[1]) + (red[2] + red[3]) + (red[4] + red[5]);

    const float var = ssq * (1.0f / 767.0f);
    const float inv = 1.0f / (sqrtf(var) + 1e-12f);

    float4 o;
    o.x = d0 * inv; o.y = d1 * inv; o.z = d2 * inv; o.w = d3 * inv;
    *(float4*)(out + (size_t)rowb * DD + t * 4) = o;
}

// ---------------------------------------------------------------------------
// Launch
// ---------------------------------------------------------------------------
extern "C" void kernel_launch(void* const* d_in, const int* in_sizes, int n_in,
                              void* d_out, int out_size)
{
    const float* h  = (const float*)d_in[0];
    const float* Wq = (const float*)d_in[1];
    const float* bq = (const float*)d_in[2];
    const float* Wk = (const float*)d_in[3];
    const float* bk = (const float*)d_in[4];
    const float* Wv = (const float*)d_in[5];
    const float* bv = (const float*)d_in[6];
    const float* Wo = (const float*)d_in[7];
    const float* bo = (const float*)d_in[8];

    bf16 *hhi, *hlo, *wqh, *wql, *wkh, *wkl, *wvh, *wvl, *woh, *wol;
    bf16 *qhi, *qlo, *khi, *klo, *vhi, *vlo, *chi, *clo;
    float *hp;
    cudaGetSymbolAddress((void**)&hhi, g_hhi);  cudaGetSymbolAddress((void**)&hlo, g_hlo);
    cudaGetSymbolAddress((void**)&wqh, g_Wqhi); cudaGetSymbolAddress((void**)&wql, g_Wqlo);
    cudaGetSymbolAddress((void**)&wkh, g_Wkhi); cudaGetSymbolAddress((void**)&wkl, g_Wklo);
    cudaGetSymbolAddress((void**)&wvh, g_Wvhi); cudaGetSymbolAddress((void**)&wvl, g_Wvlo);
    cudaGetSymbolAddress((void**)&woh, g_Wohi); cudaGetSymbolAddress((void**)&wol, g_Wolo);
    cudaGetSymbolAddress((void**)&qhi, g_Qhi);  cudaGetSymbolAddress((void**)&qlo, g_Qlo);
    cudaGetSymbolAddress((void**)&khi, g_Khi);  cudaGetSymbolAddress((void**)&klo, g_Klo);
    cudaGetSymbolAddress((void**)&vhi, g_Vhi);  cudaGetSymbolAddress((void**)&vlo, g_Vlo);
    cudaGetSymbolAddress((void**)&chi, g_Chi);  cudaGetSymbolAddress((void**)&clo, g_Clo);
    cudaGetSymbolAddress((void**)&hp,  g_h);

    cudaFuncSetAttribute(gemm_qkv, cudaFuncAttributeMaxDynamicSharedMemorySize, 98304);
    cudaFuncSetAttribute(gemm_o,   cudaFuncAttributeMaxDynamicSharedMemorySize, 73728);
    cudaFuncSetAttribute(attn_mma, cudaFuncAttributeMaxDynamicSharedMemorySize, 65536);

    // hi/lo splits
    {
        int n4 = NROWS * DD / 4;
        split_kernel<<<(n4 + 255) / 256, 256>>>((const float4*)h, (uint32_t*)hhi, (uint32_t*)hlo, n4);
        int w4 = DD * DD / 4;
        split_w4<<<dim3((w4 + 255) / 256, 4), 256>>>(
            (const float4*)Wq, (const float4*)Wk, (const float4*)Wv, (const float4*)Wo,
            (uint32_t*)wqh, (uint32_t*)wql, (uint32_t*)wkh, (uint32_t*)wkl,
            (uint32_t*)wvh, (uint32_t*)wvl, (uint32_t*)woh, (uint32_t*)wol);
    }

    gemm_qkv<<<dim3(NROWS / 128, DD / 128, 3), 256, 98304>>>(
        hhi, hlo,
        wqh, wql, bq, wkh, wkl, bk, wvh, wvl, bv,
        qhi, qlo, khi, klo, vhi, vlo);

    attn_mma<<<dim3(SEQ / 128, BAT * NH), 128, 65536>>>(qhi, qlo, khi, klo, vhi, vlo, chi, clo);

    gemm_o<<<dim3(NROWS / 64, DD / 128), 256, 73728>>>(chi, clo, woh, wol, bo, h, hp);

    ln_kernel<<<NROWS, 192>>>(hp, (float*)d_out);
}

// round 9
// speedup vs baseline: 1.0332x; 1.0332x over previous
#include <cuda_runtime.h>
#include <cuda_bf16.h>
#include <math.h>
#include <stdint.h>

#define DD   768
#define NH   12
#define HDIM 64
#define SEQ  2048
#define BAT  4
#define NROWS (BAT*SEQ)   // 8192

typedef __nv_bfloat16 bf16;

// ---------------------------------------------------------------------------
// Scratch (static __device__ arrays — no allocation allowed)
// ---------------------------------------------------------------------------
__device__ bf16 g_hhi[NROWS*DD], g_hlo[NROWS*DD];
__device__ bf16 g_Wqhi[DD*DD], g_Wqlo[DD*DD];
__device__ bf16 g_Wkhi[DD*DD], g_Wklo[DD*DD];
__device__ bf16 g_Wvhi[DD*DD], g_Wvlo[DD*DD];
__device__ bf16 g_Wohi[DD*DD], g_Wolo[DD*DD];
__device__ bf16 g_Qhi[NROWS*DD], g_Qlo[NROWS*DD];   // [b,h,s,d]
__device__ bf16 g_Khi[NROWS*DD], g_Klo[NROWS*DD];   // [b,h,s,d]
__device__ bf16 g_Vhi[NROWS*DD], g_Vlo[NROWS*DD];   // [b,h,s,d]
__device__ bf16 g_Chi[NROWS*DD], g_Clo[NROWS*DD];   // [b*s, d_model]
__device__ float g_h[NROWS*DD];                     // pre-LN fp32

// ---------------------------------------------------------------------------
// PTX helpers (sm_80-compatible: mma.sync / ldmatrix / cp.async)
// ---------------------------------------------------------------------------
__device__ __forceinline__ uint32_t smem_to_u32(const void* p) {
    uint32_t a;
    asm("{ .reg .u64 t; cvta.to.shared.u64 t, %1; cvt.u32.u64 %0, t; }" : "=r"(a) : "l"(p));
    return a;
}
#define SWZ(o) ((uint32_t)(o) ^ ((((uint32_t)(o)) >> 3) & 0x70))

__device__ __forceinline__ void cp_async16(uint32_t s, const void* g) {
    asm volatile("cp.async.cg.shared.global [%0], [%1], 16;" :: "r"(s), "l"(g) : "memory");
}
__device__ __forceinline__ void cp_commit() {
    asm volatile("cp.async.commit_group;" ::: "memory");
}
template<int N>
__device__ __forceinline__ void cp_wait() {
    asm volatile("cp.async.wait_group %0;" :: "n"(N) : "memory");
}

__device__ __forceinline__ void ldsm_x4(uint32_t* r, uint32_t a) {
    asm volatile("ldmatrix.sync.aligned.m8n8.x4.shared.b16 {%0,%1,%2,%3}, [%4];"
        : "=r"(r[0]), "=r"(r[1]), "=r"(r[2]), "=r"(r[3]) : "r"(a));
}
__device__ __forceinline__ void ldsm_x4_t(uint32_t* r, uint32_t a) {
    asm volatile("ldmatrix.sync.aligned.m8n8.x4.trans.shared.b16 {%0,%1,%2,%3}, [%4];"
        : "=r"(r[0]), "=r"(r[1]), "=r"(r[2]), "=r"(r[3]) : "r"(a));
}

// D += A * B, m16n8k16 bf16 -> fp32
__device__ __forceinline__ void mma_bf(float* d, const uint32_t* a, const uint32_t* b) {
    asm volatile("mma.sync.aligned.m16n8k16.row.col.f32.bf16.bf16.f32 "
        "{%0,%1,%2,%3}, {%4,%5,%6,%7}, {%8,%9}, {%0,%1,%2,%3};"
        : "+f"(d[0]), "+f"(d[1]), "+f"(d[2]), "+f"(d[3])
        : "r"(a[0]), "r"(a[1]), "r"(a[2]), "r"(a[3]), "r"(b[0]), "r"(b[1]));
}

// Fast hi/lo split of 2 fp32 (cvt.rn.bf16x2 + bit tricks)
__device__ __forceinline__ void split2(float v0, float v1, uint32_t& hi, uint32_t& lo) {
    uint32_t H;
    asm("cvt.rn.bf16x2.f32 %0, %1, %2;" : "=r"(H) : "f"(v1), "f"(v0));
    float h0 = __uint_as_float(H << 16);
    float h1 = __uint_as_float(H & 0xFFFF0000u);
    float l0 = v0 - h0, l1 = v1 - h1;
    uint32_t L;
    asm("cvt.rn.bf16x2.f32 %0, %1, %2;" : "=r"(L) : "f"(l1), "f"(l0));
    hi = H; lo = L;
}

// ---------------------------------------------------------------------------
// fp32 -> bf16 hi/lo split kernels
// ---------------------------------------------------------------------------
__global__ __launch_bounds__(256)
void split_kernel(const float4* __restrict__ x, uint32_t* __restrict__ hi2,
                  uint32_t* __restrict__ lo2, int n4)
{
    int i = blockIdx.x * 256 + threadIdx.x;
    if (i >= n4) return;
    float4 v = x[i];
    uint32_t h0, l0, h1, l1;
    split2(v.x, v.y, h0, l0);
    split2(v.z, v.w, h1, l1);
    uint2 H = make_uint2(h0, h1), L = make_uint2(l0, l1);
    *(uint2*)(hi2 + 2*i) = H;
    *(uint2*)(lo2 + 2*i) = L;
}

__global__ __launch_bounds__(256)
void split_w4(const float4* __restrict__ w0, const float4* __restrict__ w1,
              const float4* __restrict__ w2, const float4* __restrict__ w3,
              uint32_t* __restrict__ h0, uint32_t* __restrict__ l0,
              uint32_t* __restrict__ h1, uint32_t* __restrict__ l1,
              uint32_t* __restrict__ h2, uint32_t* __restrict__ l2,
              uint32_t* __restrict__ h3, uint32_t* __restrict__ l3)
{
    const int n4 = DD * DD / 4;
    int i = blockIdx.x * 256 + threadIdx.x;
    if (i >= n4) return;
    int wsel = blockIdx.y;
    const float4* w = wsel == 0 ? w0 : (wsel == 1 ? w1 : (wsel == 2 ? w2 : w3));
    uint32_t* hh = wsel == 0 ? h0 : (wsel == 1 ? h1 : (wsel == 2 ? h2 : h3));
    uint32_t* ll = wsel == 0 ? l0 : (wsel == 1 ? l1 : (wsel == 2 ? l2 : l3));
    float4 v = w[i];
    uint32_t a0, b0, a1, b1;
    split2(v.x, v.y, a0, b0);
    split2(v.z, v.w, a1, b1);
    uint2 H = make_uint2(a0, a1), L = make_uint2(b0, b1);
    *(uint2*)(hh + 2*i) = H;
    *(uint2*)(ll + 2*i) = L;
}

// ---------------------------------------------------------------------------
// 3xBF16 HMMA GEMM (QKV fused): C[m,o] = sum_k A[m,k]*W[o,k] + bias[o]
// CTA 128x128, 128 thr (4 warps, 2x2, warp tile 64x64), k-chunk 32,
// triple-buffered cp.async (3 x 32KB). High MMA:ldsm ratio (96:16 per k16)
// makes the mainloop MMA-bound instead of smem-bound. 2 CTAs/SM.
// ---------------------------------------------------------------------------
__global__ __launch_bounds__(128, 2)
void gemm_qkv(const bf16* __restrict__ Ahi, const bf16* __restrict__ Alo,
              const bf16* __restrict__ W0h, const bf16* __restrict__ W0l, const float* __restrict__ b0,
              const bf16* __restrict__ W1h, const bf16* __restrict__ W1l, const float* __restrict__ b1,
              const bf16* __restrict__ W2h, const bf16* __restrict__ W2l, const float* __restrict__ b2,
              bf16* __restrict__ O0h, bf16* __restrict__ O0l,
              bf16* __restrict__ O1h, bf16* __restrict__ O1l,
              bf16* __restrict__ O2h, bf16* __restrict__ O2l)
{
    extern __shared__ char smem[];
    const uint32_t sb = smem_to_u32(smem);
    const int t = threadIdx.x, lane = t & 31, wid = t >> 5;
    const int wm = wid >> 1, wn = wid & 1;      // 2x2 warp grid, 64x64 tiles
    const int nbase = blockIdx.x * 128, obase = blockIdx.y * 128;
    const int which = blockIdx.z;
    const bf16*  Bh   = which == 0 ? W0h : (which == 1 ? W1h : W2h);
    const bf16*  Bl   = which == 0 ? W0l : (which == 1 ? W1l : W2l);
    const float* bias = which == 0 ? b0  : (which == 1 ? b1  : b2);
    bf16* Oh = which == 0 ? O0h : (which == 1 ? O1h : O2h);
    bf16* Ol = which == 0 ? O0l : (which == 1 ? O1l : O2l);

    float acc[4][8][4];                          // mt x n8 x quad
    #pragma unroll
    for (int i = 0; i < 4; i++)
        #pragma unroll
        for (int j = 0; j < 8; j++)
            #pragma unroll
            for (int k = 0; k < 4; k++) acc[i][j][k] = 0.0f;

    auto prefetch = [&](int ic, int st) {
        #pragma unroll
        for (int q = 0; q < 16; q++) {
            int idx = t + 128 * q;              // 0..2047
            int rg  = idx >> 10;                // 0=A, 1=B
            int row = (idx >> 3) & 127;
            int c16 = idx & 7;                  // 0..3 hi, 4..7 lo
            uint32_t so = sb + st * 32768u + (rg ? 16384u : 0u) + SWZ(row * 128 + c16 * 16);
            const bf16* gp = rg == 0
                ? ((c16 < 4 ? Ahi : Alo) + (size_t)(nbase + row) * DD + ic * 32 + (c16 & 3) * 8)
                : ((c16 < 4 ? Bh  : Bl ) + (size_t)(obase + row) * DD + ic * 32 + (c16 & 3) * 8);
            cp_async16(so, gp);
        }
        cp_commit();
    };

    prefetch(0, 0);
    prefetch(1, 1);
    for (int ic = 0; ic < 24; ic++) {
        if (ic < 23) cp_wait<1>(); else cp_wait<0>();
        __syncthreads();
        if (ic + 2 < 24) prefetch(ic + 2, (ic + 2) % 3);

        const uint32_t sA = sb + (ic % 3) * 32768u;
        const uint32_t sB = sA + 16384u;
        #pragma unroll
        for (int k16 = 0; k16 < 2; k16++) {
            uint32_t ah[4][4], al[4][4];
            #pragma unroll
            for (int mt = 0; mt < 4; mt++) {
                int row = wm * 64 + mt * 16 + (lane & 15);
                int ch  = k16 * 2 + (lane >> 4);
                ldsm_x4(ah[mt], sA + SWZ(row * 128 + ch * 16));
                ldsm_x4(al[mt], sA + SWZ(row * 128 + (ch + 4) * 16));
            }
            #pragma unroll
            for (int ntp = 0; ntp < 4; ntp++) {
                uint32_t bh4[4], bl4[4];
                int row = wn * 64 + (ntp * 2 + (lane >> 4)) * 8 + (lane & 7);
                int ch  = k16 * 2 + ((lane >> 3) & 1);
                ldsm_x4(bh4, sB + SWZ(row * 128 + ch * 16));
                ldsm_x4(bl4, sB + SWZ(row * 128 + (ch + 4) * 16));
                #pragma unroll
                for (int mt = 0; mt < 4; mt++) {
                    mma_bf(acc[mt][2*ntp],   ah[mt], bh4 + 0);
                    mma_bf(acc[mt][2*ntp+1], ah[mt], bh4 + 2);
                    mma_bf(acc[mt][2*ntp],   ah[mt], bl4 + 0);
                    mma_bf(acc[mt][2*ntp+1], ah[mt], bl4 + 2);
                    mma_bf(acc[mt][2*ntp],   al[mt], bh4 + 0);
                    mma_bf(acc[mt][2*ntp+1], al[mt], bh4 + 2);
                }
            }
        }
    }

    // Epilogue: + bias, split hi/lo, scatter to [b,h,s,d]
    #pragma unroll
    for (int nt = 0; nt < 8; nt++) {
        const int col = obase + wn * 64 + nt * 8 + 2 * (lane & 3);
        const float2 bs = *(const float2*)(bias + col);
        const int hh = col >> 6, dd = col & 63;
        #pragma unroll
        for (int mt = 0; mt < 4; mt++) {
            const int r0 = nbase + wm * 64 + mt * 16 + (lane >> 2);
            #pragma unroll
            for (int half = 0; half < 2; half++) {
                const int r = r0 + half * 8;
                const int bb = r >> 11, ss = r & 2047;
                const size_t idx = (((size_t)(bb * NH + hh) * SEQ) + ss) * HDIM + dd;
                uint32_t H, L;
                split2(acc[mt][nt][2*half] + bs.x, acc[mt][nt][2*half+1] + bs.y, H, L);
                *(uint32_t*)(Oh + idx) = H;
                *(uint32_t*)(Ol + idx) = L;
            }
        }
    }
}

// ---------------------------------------------------------------------------
// 3xBF16 HMMA GEMM (O-proj): out fp32 = C·Wo^T + bias + residual
// 64x128 CTA tile, 256 thr, k-chunk 32, triple-buffered. Stage = 24KB.
// ---------------------------------------------------------------------------
__global__ __launch_bounds__(256, 2)
void gemm_o(const bf16* __restrict__ Ahi, const bf16* __restrict__ Alo,
            const bf16* __restrict__ Bh, const bf16* __restrict__ Bl,
            const float* __restrict__ bias, const float* __restrict__ res,
            float* __restrict__ Of)
{
    extern __shared__ char smem[];
    const uint32_t sb = smem_to_u32(smem);
    const int t = threadIdx.x, lane = t & 31, wid = t >> 5;
    const int wm = wid >> 2, wn = wid & 3;     // wm 0..1 (m32), wn 0..3 (n32)
    const int nbase = blockIdx.x * 64, obase = blockIdx.y * 128;

    float acc[2][4][4];
    #pragma unroll
    for (int i = 0; i < 2; i++)
        #pragma unroll
        for (int j = 0; j < 4; j++)
            #pragma unroll
            for (int k = 0; k < 4; k++) acc[i][j][k] = 0.0f;

    auto prefetch = [&](int ic, int st) {
        #pragma unroll
        for (int q = 0; q < 6; q++) {
            int idx = t + 256 * q;             // 0..1535
            uint32_t stage = sb + st * 24576u;
            if (idx < 512) {                   // A: 64 rows x 8 c16
                int row = idx >> 3, c16 = idx & 7;
                const bf16* gp = (c16 < 4 ? Ahi : Alo)
                    + (size_t)(nbase + row) * DD + ic * 32 + (c16 & 3) * 8;
                cp_async16(stage + SWZ(row * 128 + c16 * 16), gp);
            } else {                            // B: 128 rows x 8 c16
                int j = idx - 512;
                int row = j >> 3, c16 = j & 7;
                const bf16* gp = (c16 < 4 ? Bh : Bl)
                    + (size_t)(obase + row) * DD + ic * 32 + (c16 & 3) * 8;
                cp_async16(stage + 8192u + SWZ(row * 128 + c16 * 16), gp);
            }
        }
        cp_commit();
    };

    prefetch(0, 0);
    prefetch(1, 1);
    for (int ic = 0; ic < 24; ic++) {
        if (ic < 23) cp_wait<1>(); else cp_wait<0>();
        __syncthreads();
        if (ic + 2 < 24) prefetch(ic + 2, (ic + 2) % 3);

        const uint32_t sA = sb + (ic % 3) * 24576u;
        const uint32_t sB = sA + 8192u;
        #pragma unroll
        for (int k16 = 0; k16 < 2; k16++) {
            uint32_t ah[2][4], al[2][4];
            #pragma unroll
            for (int mt = 0; mt < 2; mt++) {
                int row = wm * 32 + mt * 16 + (lane & 15);
                int ch  = k16 * 2 + (lane >> 4);
                ldsm_x4(ah[mt], sA + SWZ(row * 128 + ch * 16));
                ldsm_x4(al[mt], sA + SWZ(row * 128 + (ch + 4) * 16));
            }
            #pragma unroll
            for (int ntp = 0; ntp < 2; ntp++) {
                uint32_t bh4[4], bl4[4];
                int row = wn * 32 + (ntp * 2 + (lane >> 4)) * 8 + (lane & 7);
                int ch  = k16 * 2 + ((lane >> 3) & 1);
                ldsm_x4(bh4, sB + SWZ(row * 128 + ch * 16));
                ldsm_x4(bl4, sB + SWZ(row * 128 + (ch + 4) * 16));
                #pragma unroll
                for (int mt = 0; mt < 2; mt++) {
                    mma_bf(acc[mt][2*ntp],   ah[mt], bh4 + 0);
                    mma_bf(acc[mt][2*ntp],   ah[mt], bl4 + 0);
                    mma_bf(acc[mt][2*ntp],   al[mt], bh4 + 0);
                    mma_bf(acc[mt][2*ntp+1], ah[mt], bh4 + 2);
                    mma_bf(acc[mt][2*ntp+1], ah[mt], bl4 + 2);
                    mma_bf(acc[mt][2*ntp+1], al[mt], bh4 + 2);
                }
            }
        }
    }

    #pragma unroll
    for (int nt = 0; nt < 4; nt++) {
        const int col = obase + wn * 32 + nt * 8 + 2 * (lane & 3);
        const float2 bs = *(const float2*)(bias + col);
        #pragma unroll
        for (int mt = 0; mt < 2; mt++) {
            const int r0 = nbase + wm * 32 + mt * 16 + (lane >> 2);
            #pragma unroll
            for (int half = 0; half < 2; half++) {
                const int r = r0 + half * 8;
                const size_t idx = (size_t)r * DD + col;
                const float2 rr = *(const float2*)(res + idx);
                float2 o;
                o.x = acc[mt][nt][2*half]   + bs.x + rr.x;
                o.y = acc[mt][nt][2*half+1] + bs.y + rr.y;
                *(float2*)(Of + idx) = o;
            }
        }
    }
}

// ---------------------------------------------------------------------------
// Flash attention (R7 config — best measured), 3xBF16 HMMA, no-max softmax.
// 64-query CTAs: grid (32, 48), 128 thr (4 warps x 16 q-rows), 32-key tiles.
// 3-stage in-place pipeline in 48KB (Q region becomes stage 2 after the
// persistent Q fragments are extracted): ONE __syncthreads per tile,
// prefetch distance 2. 4 CTAs/SM.
// ---------------------------------------------------------------------------
__global__ __launch_bounds__(128, 4)
void attn_mma(const bf16* __restrict__ Qhi, const bf16* __restrict__ Qlo,
              const bf16* __restrict__ Khi, const bf16* __restrict__ Klo,
              const bf16* __restrict__ Vhi, const bf16* __restrict__ Vlo,
              bf16* __restrict__ Chi, bf16* __restrict__ Clo)
{
    extern __shared__ char smem[];
    const uint32_t sb = smem_to_u32(smem);
    const int t = threadIdx.x, lane = t & 31, wid = t >> 5;
    const int bh = blockIdx.y, q0 = blockIdx.x * 64;
    const size_t bhoff = (size_t)bh * SEQ * HDIM;

    // Q tile (64 rows) -> stage-2 region (sb+32KB): hi at +0, lo at +8KB
    #pragma unroll
    for (int q = 0; q < 8; q++) {
        int idx = t + 128 * q;                 // 0..1023
        int rg = idx >> 9;                     // 0 hi, 1 lo
        int row = (idx >> 3) & 63;
        int c16 = idx & 7;
        uint32_t so = sb + 32768u + rg * 8192u + SWZ(row * 128 + c16 * 16);
        const bf16* gp = (rg ? Qlo : Qhi) + bhoff + (size_t)(q0 + row) * HDIM + c16 * 8;
        cp_async16(so, gp);
    }
    cp_commit();

    // KV stage (32 keys): KH 4KB | KL 4KB | VH 4KB | VL 4KB = 16KB at st*16KB
    auto prefetch_kv = [&](int kt, int st) {
        #pragma unroll
        for (int q = 0; q < 8; q++) {
            int idx = t + 128 * q;             // 0..1023
            int rg  = idx >> 8;                // 0 KH, 1 KL, 2 VH, 3 VL
            int row = (idx >> 3) & 31;
            int c16 = idx & 7;
            uint32_t so = sb + st * 16384u + rg * 4096u + SWZ(row * 128 + c16 * 16);
            const bf16* base = rg == 0 ? Khi : (rg == 1 ? Klo : (rg == 2 ? Vhi : Vlo));
            cp_async16(so, base + bhoff + (size_t)(kt * 32 + row) * HDIM + c16 * 8);
        }
        cp_commit();
    };

    prefetch_kv(0, 0);
    prefetch_kv(1, 1);
    cp_wait<1>();        // Q + kv0 done (kv1 may still be in flight)
    __syncthreads();

    // Q fragments (persistent) from stage-2 region
    uint32_t qh[4][4], ql[4][4];
    #pragma unroll
    for (int k16 = 0; k16 < 4; k16++) {
        int row = wid * 16 + (lane & 15);
        int ch  = k16 * 2 + (lane >> 4);
        ldsm_x4(qh[k16], sb + 32768u + SWZ(row * 128 + ch * 16));
        ldsm_x4(ql[k16], sb + 32768u + 8192u + SWZ(row * 128 + ch * 16));
    }
    __syncthreads();     // all warps done reading Q before stage 2 is reused

    float oacc[8][4];
    #pragma unroll
    for (int i = 0; i < 8; i++)
        #pragma unroll
        for (int j = 0; j < 4; j++) oacc[i][j] = 0.0f;
    float lsum0 = 0.0f, lsum1 = 0.0f;

    for (int kt = 0; kt < 64; kt++) {
        if (kt > 0) {
            if (kt < 63) cp_wait<1>(); else cp_wait<0>();
            __syncthreads();   // stage kt ready; stage kt-1 fully consumed
        }
        if (kt + 2 < 64) prefetch_kv(kt + 2, (kt + 2) % 3);

        const uint32_t sKH = sb + (uint32_t)(kt % 3) * 16384u;
        const uint32_t sKL = sKH + 4096u;
        const uint32_t sVH = sKH + 8192u;
        const uint32_t sVL = sKH + 12288u;

        // S = Q·K^T over 32 keys (2 ntp x 2 n8)
        float sacc[4][4];
        #pragma unroll
        for (int i = 0; i < 4; i++)
            #pragma unroll
            for (int j = 0; j < 4; j++) sacc[i][j] = 0.0f;

        #pragma unroll
        for (int ntp = 0; ntp < 2; ntp++) {
            #pragma unroll
            for (int k16 = 0; k16 < 4; k16++) {
                uint32_t kh4[4], kl4[4];
                int row = (ntp * 2 + (lane >> 4)) * 8 + (lane & 7);
                int ch  = k16 * 2 + ((lane >> 3) & 1);
                ldsm_x4(kh4, sKH + SWZ(row * 128 + ch * 16));
                ldsm_x4(kl4, sKL + SWZ(row * 128 + ch * 16));
                mma_bf(sacc[2*ntp],   qh[k16], kh4 + 0);
                mma_bf(sacc[2*ntp],   qh[k16], kl4 + 0);
                mma_bf(sacc[2*ntp],   ql[k16], kh4 + 0);
                mma_bf(sacc[2*ntp+1], qh[k16], kh4 + 2);
                mma_bf(sacc[2*ntp+1], qh[k16], kl4 + 2);
                mma_bf(sacc[2*ntp+1], ql[k16], kh4 + 2);
            }
        }

        // exp (no shift) + pack P as A-fragments (hi/lo)
        uint32_t ph[2][4], pl[2][4];
        #pragma unroll
        for (int pp = 0; pp < 2; pp++) {
            float e[8];
            #pragma unroll
            for (int j = 0; j < 4; j++) {
                e[j]     = __expf(sacc[2*pp][j]);
                e[4 + j] = __expf(sacc[2*pp+1][j]);
            }
            lsum0 += (e[0] + e[1]) + (e[4] + e[5]);
            lsum1 += (e[2] + e[3]) + (e[6] + e[7]);
            split2(e[0], e[1], ph[pp][0], pl[pp][0]);
            split2(e[2], e[3], ph[pp][1], pl[pp][1]);
            split2(e[4], e[5], ph[pp][2], pl[pp][2]);
            split2(e[6], e[7], ph[pp][3], pl[pp][3]);
        }

        // O += P·V
        #pragma unroll
        for (int pp = 0; pp < 2; pp++) {
            const int kk0 = pp * 16;
            #pragma unroll
            for (int dtp = 0; dtp < 4; dtp++) {
                uint32_t vh4[4], vl4[4];
                int row = kk0 + (lane & 15);
                int ch  = dtp * 2 + (lane >> 4);
                ldsm_x4_t(vh4, sVH + SWZ(row * 128 + ch * 16));
                ldsm_x4_t(vl4, sVL + SWZ(row * 128 + ch * 16));
                mma_bf(oacc[2*dtp],   ph[pp], vh4 + 0);
                mma_bf(oacc[2*dtp],   ph[pp], vl4 + 0);
                mma_bf(oacc[2*dtp],   pl[pp], vh4 + 0);
                mma_bf(oacc[2*dtp+1], ph[pp], vh4 + 2);
                mma_bf(oacc[2*dtp+1], ph[pp], vl4 + 2);
                mma_bf(oacc[2*dtp+1], pl[pp], vh4 + 2);
            }
        }
    }

    // Row sums across the quad, then normalize + store
    lsum0 += __shfl_xor_sync(0xffffffffu, lsum0, 1);
    lsum0 += __shfl_xor_sync(0xffffffffu, lsum0, 2);
    lsum1 += __shfl_xor_sync(0xffffffffu, lsum1, 1);
    lsum1 += __shfl_xor_sync(0xffffffffu, lsum1, 2);
    const float inv0 = 1.0f / lsum0, inv1 = 1.0f / lsum1;
    const int bb = bh / NH, hh = bh % NH;
    const int r0 = q0 + wid * 16 + (lane >> 2);
    #pragma unroll
    for (int dt = 0; dt < 8; dt++) {
        const int col = hh * 64 + dt * 8 + 2 * (lane & 3);
        const size_t i0 = ((size_t)(bb * SEQ) + r0) * DD + col;
        const size_t i1 = i0 + (size_t)8 * DD;
        uint32_t H, L;
        split2(oacc[dt][0] * inv0, oacc[dt][1] * inv0, H, L);
        *(uint32_t*)(Chi + i0) = H; *(uint32_t*)(Clo + i0) = L;
        split2(oacc[dt][2] * inv1, oacc[dt][3] * inv1, H, L);
        *(uint32_t*)(Chi + i1) = H; *(uint32_t*)(Clo + i1) = L;
    }
}

// ---------------------------------------------------------------------------
// LayerNorm (custom): mean, unbiased std (ddof=1), (x-mean)/(std+eps)
// ---------------------------------------------------------------------------
__global__ __launch_bounds__(192)
void ln_kernel(const float* __restrict__ Hin, float* __restrict__ out)
{
    __shared__ float red[6];
    const int rowb = blockIdx.x;
    const int t = threadIdx.x;
    const float4 v = *(const float4*)(Hin + (size_t)rowb * DD + t * 4);

    float s = (v.x + v.y) + (v.z + v.w);
    #pragma unroll
    for (int off = 16; off >= 1; off >>= 1) s += __shfl_xor_sync(0xffffffffu, s, off);
    if ((t & 31) == 0) red[t >> 5] = s;
    __syncthreads();
    float tot = (red[0] + red[1]) + (red[2] + red[3]) + (red[4] + red[5]);
    const float mean = tot * (1.0f / 768.0f);

    float d0 = v.x - mean, d1 = v.y - mean, d2 = v.z - mean, d3 = v.w - mean;
    float sq = (d0 * d0 + d1 * d1) + (d2 * d2 + d3 * d3);
    #pragma unroll
    for (int off = 16; off >= 1; off >>= 1) sq += __shfl_xor_sync(0xffffffffu, sq, off);
    __syncthreads();
    if ((t & 31) == 0) red[t >> 5] = sq;
    __syncthreads();
    float ssq = (red[0] + red[1]) + (red[2] + red[3]) + (red[4] + red[5]);

    const float var = ssq * (1.0f / 767.0f);
    const float inv = 1.0f / (sqrtf(var) + 1e-12f);

    float4 o;
    o.x = d0 * inv; o.y = d1 * inv; o.z = d2 * inv; o.w = d3 * inv;
    *(float4*)(out + (size_t)rowb * DD + t * 4) = o;
}

// ---------------------------------------------------------------------------
// Launch
// ---------------------------------------------------------------------------
extern "C" void kernel_launch(void* const* d_in, const int* in_sizes, int n_in,
                              void* d_out, int out_size)
{
    const float* h  = (const float*)d_in[0];
    const float* Wq = (const float*)d_in[1];
    const float* bq = (const float*)d_in[2];
    const float* Wk = (const float*)d_in[3];
    const float* bk = (const float*)d_in[4];
    const float* Wv = (const float*)d_in[5];
    const float* bv = (const float*)d_in[6];
    const float* Wo = (const float*)d_in[7];
    const float* bo = (const float*)d_in[8];

    bf16 *hhi, *hlo, *wqh, *wql, *wkh, *wkl, *wvh, *wvl, *woh, *wol;
    bf16 *qhi, *qlo, *khi, *klo, *vhi, *vlo, *chi, *clo;
    float *hp;
    cudaGetSymbolAddress((void**)&hhi, g_hhi);  cudaGetSymbolAddress((void**)&hlo, g_hlo);
    cudaGetSymbolAddress((void**)&wqh, g_Wqhi); cudaGetSymbolAddress((void**)&wql, g_Wqlo);
    cudaGetSymbolAddress((void**)&wkh, g_Wkhi); cudaGetSymbolAddress((void**)&wkl, g_Wklo);
    cudaGetSymbolAddress((void**)&wvh, g_Wvhi); cudaGetSymbolAddress((void**)&wvl, g_Wvlo);
    cudaGetSymbolAddress((void**)&woh, g_Wohi); cudaGetSymbolAddress((void**)&wol, g_Wolo);
    cudaGetSymbolAddress((void**)&qhi, g_Qhi);  cudaGetSymbolAddress((void**)&qlo, g_Qlo);
    cudaGetSymbolAddress((void**)&khi, g_Khi);  cudaGetSymbolAddress((void**)&klo, g_Klo);
    cudaGetSymbolAddress((void**)&vhi, g_Vhi);  cudaGetSymbolAddress((void**)&vlo, g_Vlo);
    cudaGetSymbolAddress((void**)&chi, g_Chi);  cudaGetSymbolAddress((void**)&clo, g_Clo);
    cudaGetSymbolAddress((void**)&hp,  g_h);

    cudaFuncSetAttribute(gemm_qkv, cudaFuncAttributeMaxDynamicSharedMemorySize, 98304);
    cudaFuncSetAttribute(gemm_o,   cudaFuncAttributeMaxDynamicSharedMemorySize, 73728);
    cudaFuncSetAttribute(attn_mma, cudaFuncAttributeMaxDynamicSharedMemorySize, 49152);

    // hi/lo splits
    {
        int n4 = NROWS * DD / 4;
        split_kernel<<<(n4 + 255) / 256, 256>>>((const float4*)h, (uint32_t*)hhi, (uint32_t*)hlo, n4);
        int w4 = DD * DD / 4;
        split_w4<<<dim3((w4 + 255) / 256, 4), 256>>>(
            (const float4*)Wq, (const float4*)Wk, (const float4*)Wv, (const float4*)Wo,
            (uint32_t*)wqh, (uint32_t*)wql, (uint32_t*)wkh, (uint32_t*)wkl,
            (uint32_t*)wvh, (uint32_t*)wvl, (uint32_t*)woh, (uint32_t*)wol);
    }

    gemm_qkv<<<dim3(NROWS / 128, DD / 128, 3), 128, 98304>>>(
        hhi, hlo,
        wqh, wql, bq, wkh, wkl, bk, wvh, wvl, bv,
        qhi, qlo, khi, klo, vhi, vlo);

    attn_mma<<<dim3(SEQ / 64, BAT * NH), 128, 49152>>>(qhi, qlo, khi, klo, vhi, vlo, chi, clo);

    gemm_o<<<dim3(NROWS / 64, DD / 128), 256, 73728>>>(chi, clo, woh, wol, bo, h, hp);

    ln_kernel<<<NROWS, 192>>>(hp, (float*)d_out);
}

// round 10
// speedup vs baseline: 1.0357x; 1.0024x over previous
#include <cuda_runtime.h>
#include <cuda_bf16.h>
#include <math.h>
#include <stdint.h>

#define DD   768
#define NH   12
#define HDIM 64
#define SEQ  2048
#define BAT  4
#define NROWS (BAT*SEQ)   // 8192

typedef __nv_bfloat16 bf16;

// ---------------------------------------------------------------------------
// Scratch (static __device__ arrays — no allocation allowed)
// ---------------------------------------------------------------------------
__device__ bf16 g_hhi[NROWS*DD], g_hlo[NROWS*DD];
__device__ bf16 g_Wqhi[DD*DD], g_Wqlo[DD*DD];
__device__ bf16 g_Wkhi[DD*DD], g_Wklo[DD*DD];
__device__ bf16 g_Wvhi[DD*DD], g_Wvlo[DD*DD];
__device__ bf16 g_Wohi[DD*DD], g_Wolo[DD*DD];
__device__ bf16 g_Qhi[NROWS*DD], g_Qlo[NROWS*DD];   // [b,h,s,d]
__device__ bf16 g_Khi[NROWS*DD], g_Klo[NROWS*DD];   // [b,h,s,d]
__device__ bf16 g_Vhi[NROWS*DD], g_Vlo[NROWS*DD];   // [b,h,s,d]
__device__ bf16 g_Chi[NROWS*DD], g_Clo[NROWS*DD];   // [b*s, d_model]
__device__ float g_h[NROWS*DD];                     // pre-LN fp32

// ---------------------------------------------------------------------------
// PTX helpers (sm_80-compatible: mma.sync / ldmatrix / cp.async)
// ---------------------------------------------------------------------------
__device__ __forceinline__ uint32_t smem_to_u32(const void* p) {
    uint32_t a;
    asm("{ .reg .u64 t; cvta.to.shared.u64 t, %1; cvt.u32.u64 %0, t; }" : "=r"(a) : "l"(p));
    return a;
}
#define SWZ(o) ((uint32_t)(o) ^ ((((uint32_t)(o)) >> 3) & 0x70))

__device__ __forceinline__ void cp_async16(uint32_t s, const void* g) {
    asm volatile("cp.async.cg.shared.global [%0], [%1], 16;" :: "r"(s), "l"(g) : "memory");
}
__device__ __forceinline__ void cp_commit() {
    asm volatile("cp.async.commit_group;" ::: "memory");
}
template<int N>
__device__ __forceinline__ void cp_wait() {
    asm volatile("cp.async.wait_group %0;" :: "n"(N) : "memory");
}

__device__ __forceinline__ void ldsm_x4(uint32_t* r, uint32_t a) {
    asm volatile("ldmatrix.sync.aligned.m8n8.x4.shared.b16 {%0,%1,%2,%3}, [%4];"
        : "=r"(r[0]), "=r"(r[1]), "=r"(r[2]), "=r"(r[3]) : "r"(a));
}
__device__ __forceinline__ void ldsm_x4_t(uint32_t* r, uint32_t a) {
    asm volatile("ldmatrix.sync.aligned.m8n8.x4.trans.shared.b16 {%0,%1,%2,%3}, [%4];"
        : "=r"(r[0]), "=r"(r[1]), "=r"(r[2]), "=r"(r[3]) : "r"(a));
}

// D += A * B, m16n8k16 bf16 -> fp32
__device__ __forceinline__ void mma_bf(float* d, const uint32_t* a, const uint32_t* b) {
    asm volatile("mma.sync.aligned.m16n8k16.row.col.f32.bf16.bf16.f32 "
        "{%0,%1,%2,%3}, {%4,%5,%6,%7}, {%8,%9}, {%0,%1,%2,%3};"
        : "+f"(d[0]), "+f"(d[1]), "+f"(d[2]), "+f"(d[3])
        : "r"(a[0]), "r"(a[1]), "r"(a[2]), "r"(a[3]), "r"(b[0]), "r"(b[1]));
}

// Fast hi/lo split of 2 fp32 (cvt.rn.bf16x2 + bit tricks)
__device__ __forceinline__ void split2(float v0, float v1, uint32_t& hi, uint32_t& lo) {
    uint32_t H;
    asm("cvt.rn.bf16x2.f32 %0, %1, %2;" : "=r"(H) : "f"(v1), "f"(v0));
    float h0 = __uint_as_float(H << 16);
    float h1 = __uint_as_float(H & 0xFFFF0000u);
    float l0 = v0 - h0, l1 = v1 - h1;
    uint32_t L;
    asm("cvt.rn.bf16x2.f32 %0, %1, %2;" : "=r"(L) : "f"(l1), "f"(l0));
    hi = H; lo = L;
}

// ---------------------------------------------------------------------------
// Fused fp32 -> bf16 hi/lo split: hidden (index < N4H) + 4 weights, one launch
// ---------------------------------------------------------------------------
#define N4H (NROWS * DD / 4)      // 1572864
#define W4  (DD * DD / 4)         // 147456
#define N4TOT (N4H + 4 * W4)      // 2162688

__global__ __launch_bounds__(256)
void split_all(const float4* __restrict__ xh,
               const float4* __restrict__ w0, const float4* __restrict__ w1,
               const float4* __restrict__ w2, const float4* __restrict__ w3,
               uint32_t* __restrict__ hh, uint32_t* __restrict__ hl,
               uint32_t* __restrict__ h0, uint32_t* __restrict__ l0,
               uint32_t* __restrict__ h1, uint32_t* __restrict__ l1,
               uint32_t* __restrict__ h2, uint32_t* __restrict__ l2,
               uint32_t* __restrict__ h3, uint32_t* __restrict__ l3)
{
    int i = blockIdx.x * 256 + threadIdx.x;
    if (i >= N4TOT) return;
    const float4* src;
    uint32_t *dh, *dl;
    int r;
    if (i < N4H) {
        src = xh; dh = hh; dl = hl; r = i;
    } else {
        int j = i - N4H;
        int w = j / W4;
        r = j - w * W4;
        src = w == 0 ? w0 : (w == 1 ? w1 : (w == 2 ? w2 : w3));
        dh  = w == 0 ? h0 : (w == 1 ? h1 : (w == 2 ? h2 : h3));
        dl  = w == 0 ? l0 : (w == 1 ? l1 : (w == 2 ? l2 : l3));
    }
    float4 v = src[r];
    uint32_t a0, b0, a1, b1;
    split2(v.x, v.y, a0, b0);
    split2(v.z, v.w, a1, b1);
    uint2 H = make_uint2(a0, a1), L = make_uint2(b0, b1);
    *(uint2*)(dh + 2*r) = H;
    *(uint2*)(dl + 2*r) = L;
}

// ---------------------------------------------------------------------------
// 3xBF16 HMMA GEMM (QKV fused): C[m,o] = sum_k A[m,k]*W[o,k] + bias[o]
// CTA 128x128, 128 thr (4 warps, 2x2, warp tile 64x64), k-chunk 32,
// triple-buffered cp.async (3 x 32KB). MMA-bound mainloop. 2 CTAs/SM.
// ---------------------------------------------------------------------------
__global__ __launch_bounds__(128, 2)
void gemm_qkv(const bf16* __restrict__ Ahi, const bf16* __restrict__ Alo,
              const bf16* __restrict__ W0h, const bf16* __restrict__ W0l, const float* __restrict__ b0,
              const bf16* __restrict__ W1h, const bf16* __restrict__ W1l, const float* __restrict__ b1,
              const bf16* __restrict__ W2h, const bf16* __restrict__ W2l, const float* __restrict__ b2,
              bf16* __restrict__ O0h, bf16* __restrict__ O0l,
              bf16* __restrict__ O1h, bf16* __restrict__ O1l,
              bf16* __restrict__ O2h, bf16* __restrict__ O2l)
{
    extern __shared__ char smem[];
    const uint32_t sb = smem_to_u32(smem);
    const int t = threadIdx.x, lane = t & 31, wid = t >> 5;
    const int wm = wid >> 1, wn = wid & 1;      // 2x2 warp grid, 64x64 tiles
    const int nbase = blockIdx.x * 128, obase = blockIdx.y * 128;
    const int which = blockIdx.z;
    const bf16*  Bh   = which == 0 ? W0h : (which == 1 ? W1h : W2h);
    const bf16*  Bl   = which == 0 ? W0l : (which == 1 ? W1l : W2l);
    const float* bias = which == 0 ? b0  : (which == 1 ? b1  : b2);
    bf16* Oh = which == 0 ? O0h : (which == 1 ? O1h : O2h);
    bf16* Ol = which == 0 ? O0l : (which == 1 ? O1l : O2l);

    float acc[4][8][4];                          // mt x n8 x quad
    #pragma unroll
    for (int i = 0; i < 4; i++)
        #pragma unroll
        for (int j = 0; j < 8; j++)
            #pragma unroll
            for (int k = 0; k < 4; k++) acc[i][j][k] = 0.0f;

    auto prefetch = [&](int ic, int st) {
        #pragma unroll
        for (int q = 0; q < 16; q++) {
            int idx = t + 128 * q;              // 0..2047
            int rg  = idx >> 10;                // 0=A, 1=B
            int row = (idx >> 3) & 127;
            int c16 = idx & 7;                  // 0..3 hi, 4..7 lo
            uint32_t so = sb + st * 32768u + (rg ? 16384u : 0u) + SWZ(row * 128 + c16 * 16);
            const bf16* gp = rg == 0
                ? ((c16 < 4 ? Ahi : Alo) + (size_t)(nbase + row) * DD + ic * 32 + (c16 & 3) * 8)
                : ((c16 < 4 ? Bh  : Bl ) + (size_t)(obase + row) * DD + ic * 32 + (c16 & 3) * 8);
            cp_async16(so, gp);
        }
        cp_commit();
    };

    prefetch(0, 0);
    prefetch(1, 1);
    for (int ic = 0; ic < 24; ic++) {
        if (ic < 23) cp_wait<1>(); else cp_wait<0>();
        __syncthreads();
        if (ic + 2 < 24) prefetch(ic + 2, (ic + 2) % 3);

        const uint32_t sA = sb + (ic % 3) * 32768u;
        const uint32_t sB = sA + 16384u;
        #pragma unroll
        for (int k16 = 0; k16 < 2; k16++) {
            uint32_t ah[4][4], al[4][4];
            #pragma unroll
            for (int mt = 0; mt < 4; mt++) {
                int row = wm * 64 + mt * 16 + (lane & 15);
                int ch  = k16 * 2 + (lane >> 4);
                ldsm_x4(ah[mt], sA + SWZ(row * 128 + ch * 16));
                ldsm_x4(al[mt], sA + SWZ(row * 128 + (ch + 4) * 16));
            }
            #pragma unroll
            for (int ntp = 0; ntp < 4; ntp++) {
                uint32_t bh4[4], bl4[4];
                int row = wn * 64 + (ntp * 2 + (lane >> 4)) * 8 + (lane & 7);
                int ch  = k16 * 2 + ((lane >> 3) & 1);
                ldsm_x4(bh4, sB + SWZ(row * 128 + ch * 16));
                ldsm_x4(bl4, sB + SWZ(row * 128 + (ch + 4) * 16));
                #pragma unroll
                for (int mt = 0; mt < 4; mt++) {
                    mma_bf(acc[mt][2*ntp],   ah[mt], bh4 + 0);
                    mma_bf(acc[mt][2*ntp+1], ah[mt], bh4 + 2);
                    mma_bf(acc[mt][2*ntp],   ah[mt], bl4 + 0);
                    mma_bf(acc[mt][2*ntp+1], ah[mt], bl4 + 2);
                    mma_bf(acc[mt][2*ntp],   al[mt], bh4 + 0);
                    mma_bf(acc[mt][2*ntp+1], al[mt], bh4 + 2);
                }
            }
        }
    }

    // Epilogue: + bias, split hi/lo, scatter to [b,h,s,d]
    #pragma unroll
    for (int nt = 0; nt < 8; nt++) {
        const int col = obase + wn * 64 + nt * 8 + 2 * (lane & 3);
        const float2 bs = *(const float2*)(bias + col);
        const int hh = col >> 6, dd = col & 63;
        #pragma unroll
        for (int mt = 0; mt < 4; mt++) {
            const int r0 = nbase + wm * 64 + mt * 16 + (lane >> 2);
            #pragma unroll
            for (int half = 0; half < 2; half++) {
                const int r = r0 + half * 8;
                const int bb = r >> 11, ss = r & 2047;
                const size_t idx = (((size_t)(bb * NH + hh) * SEQ) + ss) * HDIM + dd;
                uint32_t H, L;
                split2(acc[mt][nt][2*half] + bs.x, acc[mt][nt][2*half+1] + bs.y, H, L);
                *(uint32_t*)(Oh + idx) = H;
                *(uint32_t*)(Ol + idx) = L;
            }
        }
    }
}

// ---------------------------------------------------------------------------
// 3xBF16 HMMA GEMM (O-proj): out fp32 = C·Wo^T + bias + residual
// 64x128 CTA tile, 128 thr (4 warps, 2x2, warp tile 32x64), k-chunk 32,
// triple-buffered (3 x 24KB = 72KB) -> 3 CTAs/SM, waves 768/444 = 1.73.
// ---------------------------------------------------------------------------
__global__ __launch_bounds__(128, 3)
void gemm_o(const bf16* __restrict__ Ahi, const bf16* __restrict__ Alo,
            const bf16* __restrict__ Bh, const bf16* __restrict__ Bl,
            const float* __restrict__ bias, const float* __restrict__ res,
            float* __restrict__ Of)
{
    extern __shared__ char smem[];
    const uint32_t sb = smem_to_u32(smem);
    const int t = threadIdx.x, lane = t & 31, wid = t >> 5;
    const int wm = wid >> 1, wn = wid & 1;     // 2x2 warp grid, 32x64 tiles
    const int nbase = blockIdx.x * 64, obase = blockIdx.y * 128;

    float acc[2][8][4];
    #pragma unroll
    for (int i = 0; i < 2; i++)
        #pragma unroll
        for (int j = 0; j < 8; j++)
            #pragma unroll
            for (int k = 0; k < 4; k++) acc[i][j][k] = 0.0f;

    auto prefetch = [&](int ic, int st) {
        #pragma unroll
        for (int q = 0; q < 12; q++) {
            int idx = t + 128 * q;             // 0..1535
            uint32_t stage = sb + st * 24576u;
            if (idx < 512) {                   // A: 64 rows x 8 c16
                int row = idx >> 3, c16 = idx & 7;
                const bf16* gp = (c16 < 4 ? Ahi : Alo)
                    + (size_t)(nbase + row) * DD + ic * 32 + (c16 & 3) * 8;
                cp_async16(stage + SWZ(row * 128 + c16 * 16), gp);
            } else {                            // B: 128 rows x 8 c16
                int j = idx - 512;
                int row = j >> 3, c16 = j & 7;
                const bf16* gp = (c16 < 4 ? Bh : Bl)
                    + (size_t)(obase + row) * DD + ic * 32 + (c16 & 3) * 8;
                cp_async16(stage + 8192u + SWZ(row * 128 + c16 * 16), gp);
            }
        }
        cp_commit();
    };

    prefetch(0, 0);
    prefetch(1, 1);
    for (int ic = 0; ic < 24; ic++) {
        if (ic < 23) cp_wait<1>(); else cp_wait<0>();
        __syncthreads();
        if (ic + 2 < 24) prefetch(ic + 2, (ic + 2) % 3);

        const uint32_t sA = sb + (ic % 3) * 24576u;
        const uint32_t sB = sA + 8192u;
        #pragma unroll
        for (int k16 = 0; k16 < 2; k16++) {
            uint32_t ah[2][4], al[2][4];
            #pragma unroll
            for (int mt = 0; mt < 2; mt++) {
                int row = wm * 32 + mt * 16 + (lane & 15);
                int ch  = k16 * 2 + (lane >> 4);
                ldsm_x4(ah[mt], sA + SWZ(row * 128 + ch * 16));
                ldsm_x4(al[mt], sA + SWZ(row * 128 + (ch + 4) * 16));
            }
            #pragma unroll
            for (int ntp = 0; ntp < 4; ntp++) {
                uint32_t bh4[4], bl4[4];
                int row = wn * 64 + (ntp * 2 + (lane >> 4)) * 8 + (lane & 7);
                int ch  = k16 * 2 + ((lane >> 3) & 1);
                ldsm_x4(bh4, sB + SWZ(row * 128 + ch * 16));
                ldsm_x4(bl4, sB + SWZ(row * 128 + (ch + 4) * 16));
                #pragma unroll
                for (int mt = 0; mt < 2; mt++) {
                    mma_bf(acc[mt][2*ntp],   ah[mt], bh4 + 0);
                    mma_bf(acc[mt][2*ntp+1], ah[mt], bh4 + 2);
                    mma_bf(acc[mt][2*ntp],   ah[mt], bl4 + 0);
                    mma_bf(acc[mt][2*ntp+1], ah[mt], bl4 + 2);
                    mma_bf(acc[mt][2*ntp],   al[mt], bh4 + 0);
                    mma_bf(acc[mt][2*ntp+1], al[mt], bh4 + 2);
                }
            }
        }
    }

    #pragma unroll
    for (int nt = 0; nt < 8; nt++) {
        const int col = obase + wn * 64 + nt * 8 + 2 * (lane & 3);
        const float2 bs = *(const float2*)(bias + col);
        #pragma unroll
        for (int mt = 0; mt < 2; mt++) {
            const int r0 = nbase + wm * 32 + mt * 16 + (lane >> 2);
            #pragma unroll
            for (int half = 0; half < 2; half++) {
                const int r = r0 + half * 8;
                const size_t idx = (size_t)r * DD + col;
                const float2 rr = *(const float2*)(res + idx);
                float2 o;
                o.x = acc[mt][nt][2*half]   + bs.x + rr.x;
                o.y = acc[mt][nt][2*half+1] + bs.y + rr.y;
                *(float2*)(Of + idx) = o;
            }
        }
    }
}

// ---------------------------------------------------------------------------
// Flash attention (R7/R9 config — best measured), 3xBF16 HMMA, no-max softmax.
// 64-query CTAs: grid (32, 48), 128 thr (4 warps x 16 q-rows), 32-key tiles.
// 3-stage in-place pipeline in 48KB, ONE __syncthreads per tile, 4 CTAs/SM.
// ---------------------------------------------------------------------------
__global__ __launch_bounds__(128, 4)
void attn_mma(const bf16* __restrict__ Qhi, const bf16* __restrict__ Qlo,
              const bf16* __restrict__ Khi, const bf16* __restrict__ Klo,
              const bf16* __restrict__ Vhi, const bf16* __restrict__ Vlo,
              bf16* __restrict__ Chi, bf16* __restrict__ Clo)
{
    extern __shared__ char smem[];
    const uint32_t sb = smem_to_u32(smem);
    const int t = threadIdx.x, lane = t & 31, wid = t >> 5;
    const int bh = blockIdx.y, q0 = blockIdx.x * 64;
    const size_t bhoff = (size_t)bh * SEQ * HDIM;

    // Q tile (64 rows) -> stage-2 region (sb+32KB): hi at +0, lo at +8KB
    #pragma unroll
    for (int q = 0; q < 8; q++) {
        int idx = t + 128 * q;                 // 0..1023
        int rg = idx >> 9;                     // 0 hi, 1 lo
        int row = (idx >> 3) & 63;
        int c16 = idx & 7;
        uint32_t so = sb + 32768u + rg * 8192u + SWZ(row * 128 + c16 * 16);
        const bf16* gp = (rg ? Qlo : Qhi) + bhoff + (size_t)(q0 + row) * HDIM + c16 * 8;
        cp_async16(so, gp);
    }
    cp_commit();

    // KV stage (32 keys): KH 4KB | KL 4KB | VH 4KB | VL 4KB = 16KB at st*16KB
    auto prefetch_kv = [&](int kt, int st) {
        #pragma unroll
        for (int q = 0; q < 8; q++) {
            int idx = t + 128 * q;             // 0..1023
            int rg  = idx >> 8;                // 0 KH, 1 KL, 2 VH, 3 VL
            int row = (idx >> 3) & 31;
            int c16 = idx & 7;
            uint32_t so = sb + st * 16384u + rg * 4096u + SWZ(row * 128 + c16 * 16);
            const bf16* base = rg == 0 ? Khi : (rg == 1 ? Klo : (rg == 2 ? Vhi : Vlo));
            cp_async16(so, base + bhoff + (size_t)(kt * 32 + row) * HDIM + c16 * 8);
        }
        cp_commit();
    };

    prefetch_kv(0, 0);
    prefetch_kv(1, 1);
    cp_wait<1>();        // Q + kv0 done (kv1 may still be in flight)
    __syncthreads();

    // Q fragments (persistent) from stage-2 region
    uint32_t qh[4][4], ql[4][4];
    #pragma unroll
    for (int k16 = 0; k16 < 4; k16++) {
        int row = wid * 16 + (lane & 15);
        int ch  = k16 * 2 + (lane >> 4);
        ldsm_x4(qh[k16], sb + 32768u + SWZ(row * 128 + ch * 16));
        ldsm_x4(ql[k16], sb + 32768u + 8192u + SWZ(row * 128 + ch * 16));
    }
    __syncthreads();     // all warps done reading Q before stage 2 is reused

    float oacc[8][4];
    #pragma unroll
    for (int i = 0; i < 8; i++)
        #pragma unroll
        for (int j = 0; j < 4; j++) oacc[i][j] = 0.0f;
    float lsum0 = 0.0f, lsum1 = 0.0f;

    for (int kt = 0; kt < 64; kt++) {
        if (kt > 0) {
            if (kt < 63) cp_wait<1>(); else cp_wait<0>();
            __syncthreads();   // stage kt ready; stage kt-1 fully consumed
        }
        if (kt + 2 < 64) prefetch_kv(kt + 2, (kt + 2) % 3);

        const uint32_t sKH = sb + (uint32_t)(kt % 3) * 16384u;
        const uint32_t sKL = sKH + 4096u;
        const uint32_t sVH = sKH + 8192u;
        const uint32_t sVL = sKH + 12288u;

        // S = Q·K^T over 32 keys (2 ntp x 2 n8)
        float sacc[4][4];
        #pragma unroll
        for (int i = 0; i < 4; i++)
            #pragma unroll
            for (int j = 0; j < 4; j++) sacc[i][j] = 0.0f;

        #pragma unroll
        for (int ntp = 0; ntp < 2; ntp++) {
            #pragma unroll
            for (int k16 = 0; k16 < 4; k16++) {
                uint32_t kh4[4], kl4[4];
                int row = (ntp * 2 + (lane >> 4)) * 8 + (lane & 7);
                int ch  = k16 * 2 + ((lane >> 3) & 1);
                ldsm_x4(kh4, sKH + SWZ(row * 128 + ch * 16));
                ldsm_x4(kl4, sKL + SWZ(row * 128 + ch * 16));
                mma_bf(sacc[2*ntp],   qh[k16], kh4 + 0);
                mma_bf(sacc[2*ntp],   qh[k16], kl4 + 0);
                mma_bf(sacc[2*ntp],   ql[k16], kh4 + 0);
                mma_bf(sacc[2*ntp+1], qh[k16], kh4 + 2);
                mma_bf(sacc[2*ntp+1], qh[k16], kl4 + 2);
                mma_bf(sacc[2*ntp+1], ql[k16], kh4 + 2);
            }
        }

        // exp (no shift) + pack P as A-fragments (hi/lo)
        uint32_t ph[2][4], pl[2][4];
        #pragma unroll
        for (int pp = 0; pp < 2; pp++) {
            float e[8];
            #pragma unroll
            for (int j = 0; j < 4; j++) {
                e[j]     = __expf(sacc[2*pp][j]);
                e[4 + j] = __expf(sacc[2*pp+1][j]);
            }
            lsum0 += (e[0] + e[1]) + (e[4] + e[5]);
            lsum1 += (e[2] + e[3]) + (e[6] + e[7]);
            split2(e[0], e[1], ph[pp][0], pl[pp][0]);
            split2(e[2], e[3], ph[pp][1], pl[pp][1]);
            split2(e[4], e[5], ph[pp][2], pl[pp][2]);
            split2(e[6], e[7], ph[pp][3], pl[pp][3]);
        }

        // O += P·V
        #pragma unroll
        for (int pp = 0; pp < 2; pp++) {
            const int kk0 = pp * 16;
            #pragma unroll
            for (int dtp = 0; dtp < 4; dtp++) {
                uint32_t vh4[4], vl4[4];
                int row = kk0 + (lane & 15);
                int ch  = dtp * 2 + (lane >> 4);
                ldsm_x4_t(vh4, sVH + SWZ(row * 128 + ch * 16));
                ldsm_x4_t(vl4, sVL + SWZ(row * 128 + ch * 16));
                mma_bf(oacc[2*dtp],   ph[pp], vh4 + 0);
                mma_bf(oacc[2*dtp],   ph[pp], vl4 + 0);
                mma_bf(oacc[2*dtp],   pl[pp], vh4 + 0);
                mma_bf(oacc[2*dtp+1], ph[pp], vh4 + 2);
                mma_bf(oacc[2*dtp+1], ph[pp], vl4 + 2);
                mma_bf(oacc[2*dtp+1], pl[pp], vh4 + 2);
            }
        }
    }

    // Row sums across the quad, then normalize + store
    lsum0 += __shfl_xor_sync(0xffffffffu, lsum0, 1);
    lsum0 += __shfl_xor_sync(0xffffffffu, lsum0, 2);
    lsum1 += __shfl_xor_sync(0xffffffffu, lsum1, 1);
    lsum1 += __shfl_xor_sync(0xffffffffu, lsum1, 2);
    const float inv0 = 1.0f / lsum0, inv1 = 1.0f / lsum1;
    const int bb = bh / NH, hh = bh % NH;
    const int r0 = q0 + wid * 16 + (lane >> 2);
    #pragma unroll
    for (int dt = 0; dt < 8; dt++) {
        const int col = hh * 64 + dt * 8 + 2 * (lane & 3);
        const size_t i0 = ((size_t)(bb * SEQ) + r0) * DD + col;
        const size_t i1 = i0 + (size_t)8 * DD;
        uint32_t H, L;
        split2(oacc[dt][0] * inv0, oacc[dt][1] * inv0, H, L);
        *(uint32_t*)(Chi + i0) = H; *(uint32_t*)(Clo + i0) = L;
        split2(oacc[dt][2] * inv1, oacc[dt][3] * inv1, H, L);
        *(uint32_t*)(Chi + i1) = H; *(uint32_t*)(Clo + i1) = L;
    }
}

// ---------------------------------------------------------------------------
// LayerNorm (custom): mean, unbiased std (ddof=1), (x-mean)/(std+eps)
// ---------------------------------------------------------------------------
__global__ __launch_bounds__(192)
void ln_kernel(const float* __restrict__ Hin, float* __restrict__ out)
{
    __shared__ float red[6];
    const int rowb = blockIdx.x;
    const int t = threadIdx.x;
    const float4 v = *(const float4*)(Hin + (size_t)rowb * DD + t * 4);

    float s = (v.x + v.y) + (v.z + v.w);
    #pragma unroll
    for (int off = 16; off >= 1; off >>= 1) s += __shfl_xor_sync(0xffffffffu, s, off);
    if ((t & 31) == 0) red[t >> 5] = s;
    __syncthreads();
    float tot = (red[0] + red[1]) + (red[2] + red[3]) + (red[4] + red[5]);
    const float mean = tot * (1.0f / 768.0f);

    float d0 = v.x - mean, d1 = v.y - mean, d2 = v.z - mean, d3 = v.w - mean;
    float sq = (d0 * d0 + d1 * d1) + (d2 * d2 + d3 * d3);
    #pragma unroll
    for (int off = 16; off >= 1; off >>= 1) sq += __shfl_xor_sync(0xffffffffu, sq, off);
    __syncthreads();
    if ((t & 31) == 0) red[t >> 5] = sq;
    __syncthreads();
    float ssq = (red[0] + red[1]) + (red[2] + red[3]) + (red[4] + red[5]);

    const float var = ssq * (1.0f / 767.0f);
    const float inv = 1.0f / (sqrtf(var) + 1e-12f);

    float4 o;
    o.x = d0 * inv; o.y = d1 * inv; o.z = d2 * inv; o.w = d3 * inv;
    *(float4*)(out + (size_t)rowb * DD + t * 4) = o;
}

// ---------------------------------------------------------------------------
// Launch
// ---------------------------------------------------------------------------
extern "C" void kernel_launch(void* const* d_in, const int* in_sizes, int n_in,
                              void* d_out, int out_size)
{
    const float* h  = (const float*)d_in[0];
    const float* Wq = (const float*)d_in[1];
    const float* bq = (const float*)d_in[2];
    const float* Wk = (const float*)d_in[3];
    const float* bk = (const float*)d_in[4];
    const float* Wv = (const float*)d_in[5];
    const float* bv = (const float*)d_in[6];
    const float* Wo = (const float*)d_in[7];
    const float* bo = (const float*)d_in[8];

    bf16 *hhi, *hlo, *wqh, *wql, *wkh, *wkl, *wvh, *wvl, *woh, *wol;
    bf16 *qhi, *qlo, *khi, *klo, *vhi, *vlo, *chi, *clo;
    float *hp;
    cudaGetSymbolAddress((void**)&hhi, g_hhi);  cudaGetSymbolAddress((void**)&hlo, g_hlo);
    cudaGetSymbolAddress((void**)&wqh, g_Wqhi); cudaGetSymbolAddress((void**)&wql, g_Wqlo);
    cudaGetSymbolAddress((void**)&wkh, g_Wkhi); cudaGetSymbolAddress((void**)&wkl, g_Wklo);
    cudaGetSymbolAddress((void**)&wvh, g_Wvhi); cudaGetSymbolAddress((void**)&wvl, g_Wvlo);
    cudaGetSymbolAddress((void**)&woh, g_Wohi); cudaGetSymbolAddress((void**)&wol, g_Wolo);
    cudaGetSymbolAddress((void**)&qhi, g_Qhi);  cudaGetSymbolAddress((void**)&qlo, g_Qlo);
    cudaGetSymbolAddress((void**)&khi, g_Khi);  cudaGetSymbolAddress((void**)&klo, g_Klo);
    cudaGetSymbolAddress((void**)&vhi, g_Vhi);  cudaGetSymbolAddress((void**)&vlo, g_Vlo);
    cudaGetSymbolAddress((void**)&chi, g_Chi);  cudaGetSymbolAddress((void**)&clo, g_Clo);
    cudaGetSymbolAddress((void**)&hp,  g_h);

    cudaFuncSetAttribute(gemm_qkv, cudaFuncAttributeMaxDynamicSharedMemorySize, 98304);
    cudaFuncSetAttribute(gemm_o,   cudaFuncAttributeMaxDynamicSharedMemorySize, 73728);
    cudaFuncSetAttribute(attn_mma, cudaFuncAttributeMaxDynamicSharedMemorySize, 49152);

    // Fused hi/lo splits: hidden + 4 weights in one launch
    split_all<<<(N4TOT + 255) / 256, 256>>>(
        (const float4*)h,
        (const float4*)Wq, (const float4*)Wk, (const float4*)Wv, (const float4*)Wo,
        (uint32_t*)hhi, (uint32_t*)hlo,
        (uint32_t*)wqh, (uint32_t*)wql, (uint32_t*)wkh, (uint32_t*)wkl,
        (uint32_t*)wvh, (uint32_t*)wvl, (uint32_t*)woh, (uint32_t*)wol);

    gemm_qkv<<<dim3(NROWS / 128, DD / 128, 3), 128, 98304>>>(
        hhi, hlo,
        wqh, wql, bq, wkh, wkl, bk, wvh, wvl, bv,
        qhi, qlo, khi, klo, vhi, vlo);

    attn_mma<<<dim3(SEQ / 64, BAT * NH), 128, 49152>>>(qhi, qlo, khi, klo, vhi, vlo, chi, clo);

    gemm_o<<<dim3(NROWS / 64, DD / 128), 128, 73728>>>(chi, clo, woh, wol, bo, h, hp);

    ln_kernel<<<NROWS, 192>>>(hp, (float*)d_out);
}

// round 11
// speedup vs baseline: 1.0431x; 1.0072x over previous
#include <cuda_runtime.h>
#include <cuda_bf16.h>
#include <math.h>
#include <stdint.h>

#define DD   768
#define NH   12
#define HDIM 64
#define SEQ  2048
#define BAT  4
#define NROWS (BAT*SEQ)   // 8192

typedef __nv_bfloat16 bf16;

// ---------------------------------------------------------------------------
// Scratch (static __device__ arrays — no allocation allowed)
// ---------------------------------------------------------------------------
__device__ bf16 g_hhi[NROWS*DD], g_hlo[NROWS*DD];
__device__ bf16 g_Wqhi[DD*DD], g_Wqlo[DD*DD];
__device__ bf16 g_Wkhi[DD*DD], g_Wklo[DD*DD];
__device__ bf16 g_Wvhi[DD*DD], g_Wvlo[DD*DD];
__device__ bf16 g_Wohi[DD*DD], g_Wolo[DD*DD];
__device__ bf16 g_Qhi[NROWS*DD], g_Qlo[NROWS*DD];   // [b,h,s,d]
__device__ bf16 g_Khi[NROWS*DD], g_Klo[NROWS*DD];   // [b,h,s,d]
__device__ bf16 g_Vhi[NROWS*DD], g_Vlo[NROWS*DD];   // [b,h,s,d]
__device__ bf16 g_Chi[NROWS*DD], g_Clo[NROWS*DD];   // [b*s, d_model]
__device__ float g_h[NROWS*DD];                     // pre-LN fp32 (slice 0 + bias + res)
__device__ float g_h2[NROWS*DD];                    // pre-LN fp32 (slice 1 partial)

// ---------------------------------------------------------------------------
// PTX helpers (sm_80-compatible: mma.sync / ldmatrix / cp.async)
// ---------------------------------------------------------------------------
__device__ __forceinline__ uint32_t smem_to_u32(const void* p) {
    uint32_t a;
    asm("{ .reg .u64 t; cvta.to.shared.u64 t, %1; cvt.u32.u64 %0, t; }" : "=r"(a) : "l"(p));
    return a;
}
#define SWZ(o) ((uint32_t)(o) ^ ((((uint32_t)(o)) >> 3) & 0x70))

__device__ __forceinline__ void cp_async16(uint32_t s, const void* g) {
    asm volatile("cp.async.cg.shared.global [%0], [%1], 16;" :: "r"(s), "l"(g) : "memory");
}
__device__ __forceinline__ void cp_commit() {
    asm volatile("cp.async.commit_group;" ::: "memory");
}
template<int N>
__device__ __forceinline__ void cp_wait() {
    asm volatile("cp.async.wait_group %0;" :: "n"(N) : "memory");
}

__device__ __forceinline__ void ldsm_x4(uint32_t* r, uint32_t a) {
    asm volatile("ldmatrix.sync.aligned.m8n8.x4.shared.b16 {%0,%1,%2,%3}, [%4];"
        : "=r"(r[0]), "=r"(r[1]), "=r"(r[2]), "=r"(r[3]) : "r"(a));
}
__device__ __forceinline__ void ldsm_x4_t(uint32_t* r, uint32_t a) {
    asm volatile("ldmatrix.sync.aligned.m8n8.x4.trans.shared.b16 {%0,%1,%2,%3}, [%4];"
        : "=r"(r[0]), "=r"(r[1]), "=r"(r[2]), "=r"(r[3]) : "r"(a));
}

// D += A * B, m16n8k16 bf16 -> fp32
__device__ __forceinline__ void mma_bf(float* d, const uint32_t* a, const uint32_t* b) {
    asm volatile("mma.sync.aligned.m16n8k16.row.col.f32.bf16.bf16.f32 "
        "{%0,%1,%2,%3}, {%4,%5,%6,%7}, {%8,%9}, {%0,%1,%2,%3};"
        : "+f"(d[0]), "+f"(d[1]), "+f"(d[2]), "+f"(d[3])
        : "r"(a[0]), "r"(a[1]), "r"(a[2]), "r"(a[3]), "r"(b[0]), "r"(b[1]));
}

// Fast hi/lo split of 2 fp32 (cvt.rn.bf16x2 + bit tricks)
__device__ __forceinline__ void split2(float v0, float v1, uint32_t& hi, uint32_t& lo) {
    uint32_t H;
    asm("cvt.rn.bf16x2.f32 %0, %1, %2;" : "=r"(H) : "f"(v1), "f"(v0));
    float h0 = __uint_as_float(H << 16);
    float h1 = __uint_as_float(H & 0xFFFF0000u);
    float l0 = v0 - h0, l1 = v1 - h1;
    uint32_t L;
    asm("cvt.rn.bf16x2.f32 %0, %1, %2;" : "=r"(L) : "f"(l1), "f"(l0));
    hi = H; lo = L;
}

// ---------------------------------------------------------------------------
// Fused fp32 -> bf16 hi/lo split: hidden (index < N4H) + 4 weights, one launch
// ---------------------------------------------------------------------------
#define N4H (NROWS * DD / 4)      // 1572864
#define W4  (DD * DD / 4)         // 147456
#define N4TOT (N4H + 4 * W4)      // 2162688

__global__ __launch_bounds__(256)
void split_all(const float4* __restrict__ xh,
               const float4* __restrict__ w0, const float4* __restrict__ w1,
               const float4* __restrict__ w2, const float4* __restrict__ w3,
               uint32_t* __restrict__ hh, uint32_t* __restrict__ hl,
               uint32_t* __restrict__ h0, uint32_t* __restrict__ l0,
               uint32_t* __restrict__ h1, uint32_t* __restrict__ l1,
               uint32_t* __restrict__ h2, uint32_t* __restrict__ l2,
               uint32_t* __restrict__ h3, uint32_t* __restrict__ l3)
{
    int i = blockIdx.x * 256 + threadIdx.x;
    if (i >= N4TOT) return;
    const float4* src;
    uint32_t *dh, *dl;
    int r;
    if (i < N4H) {
        src = xh; dh = hh; dl = hl; r = i;
    } else {
        int j = i - N4H;
        int w = j / W4;
        r = j - w * W4;
        src = w == 0 ? w0 : (w == 1 ? w1 : (w == 2 ? w2 : w3));
        dh  = w == 0 ? h0 : (w == 1 ? h1 : (w == 2 ? h2 : h3));
        dl  = w == 0 ? l0 : (w == 1 ? l1 : (w == 2 ? l2 : l3));
    }
    float4 v = src[r];
    uint32_t a0, b0, a1, b1;
    split2(v.x, v.y, a0, b0);
    split2(v.z, v.w, a1, b1);
    uint2 H = make_uint2(a0, a1), L = make_uint2(b0, b1);
    *(uint2*)(dh + 2*r) = H;
    *(uint2*)(dl + 2*r) = L;
}

// ---------------------------------------------------------------------------
// 3xBF16 HMMA GEMM (QKV fused): C[m,o] = sum_k A[m,k]*W[o,k] + bias[o]
// CTA 128x128, 128 thr (4 warps, 2x2, warp tile 64x64), k-chunk 32,
// triple-buffered cp.async (3 x 32KB). MMA-bound mainloop. 2 CTAs/SM.
// ---------------------------------------------------------------------------
__global__ __launch_bounds__(128, 2)
void gemm_qkv(const bf16* __restrict__ Ahi, const bf16* __restrict__ Alo,
              const bf16* __restrict__ W0h, const bf16* __restrict__ W0l, const float* __restrict__ b0,
              const bf16* __restrict__ W1h, const bf16* __restrict__ W1l, const float* __restrict__ b1,
              const bf16* __restrict__ W2h, const bf16* __restrict__ W2l, const float* __restrict__ b2,
              bf16* __restrict__ O0h, bf16* __restrict__ O0l,
              bf16* __restrict__ O1h, bf16* __restrict__ O1l,
              bf16* __restrict__ O2h, bf16* __restrict__ O2l)
{
    extern __shared__ char smem[];
    const uint32_t sb = smem_to_u32(smem);
    const int t = threadIdx.x, lane = t & 31, wid = t >> 5;
    const int wm = wid >> 1, wn = wid & 1;      // 2x2 warp grid, 64x64 tiles
    const int nbase = blockIdx.x * 128, obase = blockIdx.y * 128;
    const int which = blockIdx.z;
    const bf16*  Bh   = which == 0 ? W0h : (which == 1 ? W1h : W2h);
    const bf16*  Bl   = which == 0 ? W0l : (which == 1 ? W1l : W2l);
    const float* bias = which == 0 ? b0  : (which == 1 ? b1  : b2);
    bf16* Oh = which == 0 ? O0h : (which == 1 ? O1h : O2h);
    bf16* Ol = which == 0 ? O0l : (which == 1 ? O1l : O2l);

    float acc[4][8][4];                          // mt x n8 x quad
    #pragma unroll
    for (int i = 0; i < 4; i++)
        #pragma unroll
        for (int j = 0; j < 8; j++)
            #pragma unroll
            for (int k = 0; k < 4; k++) acc[i][j][k] = 0.0f;

    auto prefetch = [&](int ic, int st) {
        #pragma unroll
        for (int q = 0; q < 16; q++) {
            int idx = t + 128 * q;              // 0..2047
            int rg  = idx >> 10;                // 0=A, 1=B
            int row = (idx >> 3) & 127;
            int c16 = idx & 7;                  // 0..3 hi, 4..7 lo
            uint32_t so = sb + st * 32768u + (rg ? 16384u : 0u) + SWZ(row * 128 + c16 * 16);
            const bf16* gp = rg == 0
                ? ((c16 < 4 ? Ahi : Alo) + (size_t)(nbase + row) * DD + ic * 32 + (c16 & 3) * 8)
                : ((c16 < 4 ? Bh  : Bl ) + (size_t)(obase + row) * DD + ic * 32 + (c16 & 3) * 8);
            cp_async16(so, gp);
        }
        cp_commit();
    };

    prefetch(0, 0);
    prefetch(1, 1);
    for (int ic = 0; ic < 24; ic++) {
        if (ic < 23) cp_wait<1>(); else cp_wait<0>();
        __syncthreads();
        if (ic + 2 < 24) prefetch(ic + 2, (ic + 2) % 3);

        const uint32_t sA = sb + (ic % 3) * 32768u;
        const uint32_t sB = sA + 16384u;
        #pragma unroll
        for (int k16 = 0; k16 < 2; k16++) {
            uint32_t ah[4][4], al[4][4];
            #pragma unroll
            for (int mt = 0; mt < 4; mt++) {
                int row = wm * 64 + mt * 16 + (lane & 15);
                int ch  = k16 * 2 + (lane >> 4);
                ldsm_x4(ah[mt], sA + SWZ(row * 128 + ch * 16));
                ldsm_x4(al[mt], sA + SWZ(row * 128 + (ch + 4) * 16));
            }
            #pragma unroll
            for (int ntp = 0; ntp < 4; ntp++) {
                uint32_t bh4[4], bl4[4];
                int row = wn * 64 + (ntp * 2 + (lane >> 4)) * 8 + (lane & 7);
                int ch  = k16 * 2 + ((lane >> 3) & 1);
                ldsm_x4(bh4, sB + SWZ(row * 128 + ch * 16));
                ldsm_x4(bl4, sB + SWZ(row * 128 + (ch + 4) * 16));
                #pragma unroll
                for (int mt = 0; mt < 4; mt++) {
                    mma_bf(acc[mt][2*ntp],   ah[mt], bh4 + 0);
                    mma_bf(acc[mt][2*ntp+1], ah[mt], bh4 + 2);
                    mma_bf(acc[mt][2*ntp],   ah[mt], bl4 + 0);
                    mma_bf(acc[mt][2*ntp+1], ah[mt], bl4 + 2);
                    mma_bf(acc[mt][2*ntp],   al[mt], bh4 + 0);
                    mma_bf(acc[mt][2*ntp+1], al[mt], bh4 + 2);
                }
            }
        }
    }

    // Epilogue: + bias, split hi/lo, scatter to [b,h,s,d]
    #pragma unroll
    for (int nt = 0; nt < 8; nt++) {
        const int col = obase + wn * 64 + nt * 8 + 2 * (lane & 3);
        const float2 bs = *(const float2*)(bias + col);
        const int hh = col >> 6, dd = col & 63;
        #pragma unroll
        for (int mt = 0; mt < 4; mt++) {
            const int r0 = nbase + wm * 64 + mt * 16 + (lane >> 2);
            #pragma unroll
            for (int half = 0; half < 2; half++) {
                const int r = r0 + half * 8;
                const int bb = r >> 11, ss = r & 2047;
                const size_t idx = (((size_t)(bb * NH + hh) * SEQ) + ss) * HDIM + dd;
                uint32_t H, L;
                split2(acc[mt][nt][2*half] + bs.x, acc[mt][nt][2*half+1] + bs.y, H, L);
                *(uint32_t*)(Oh + idx) = H;
                *(uint32_t*)(Ol + idx) = L;
            }
        }
    }
}

// ---------------------------------------------------------------------------
// 3xBF16 HMMA GEMM (O-proj), split-K=2: same proven 128x128 / 4-warp / 64x64
// shape as gemm_qkv. blockIdx.z = K-half (384 each, 12 chunks).
// Slice 0 writes D + bias + residual -> Of0; slice 1 writes D -> Of1.
// LN sums the two partials. Deterministic (no atomics). Grid 64x6x2 = 768.
// ---------------------------------------------------------------------------
__global__ __launch_bounds__(128, 2)
void gemm_o_split(const bf16* __restrict__ Ahi, const bf16* __restrict__ Alo,
                  const bf16* __restrict__ Bh, const bf16* __restrict__ Bl,
                  const float* __restrict__ bias, const float* __restrict__ res,
                  float* __restrict__ Of0, float* __restrict__ Of1)
{
    extern __shared__ char smem[];
    const uint32_t sb = smem_to_u32(smem);
    const int t = threadIdx.x, lane = t & 31, wid = t >> 5;
    const int wm = wid >> 1, wn = wid & 1;
    const int nbase = blockIdx.x * 128, obase = blockIdx.y * 128;
    const int kbase = blockIdx.z * 384;          // K-half origin

    float acc[4][8][4];
    #pragma unroll
    for (int i = 0; i < 4; i++)
        #pragma unroll
        for (int j = 0; j < 8; j++)
            #pragma unroll
            for (int k = 0; k < 4; k++) acc[i][j][k] = 0.0f;

    auto prefetch = [&](int ic, int st) {
        #pragma unroll
        for (int q = 0; q < 16; q++) {
            int idx = t + 128 * q;              // 0..2047
            int rg  = idx >> 10;                // 0=A, 1=B
            int row = (idx >> 3) & 127;
            int c16 = idx & 7;                  // 0..3 hi, 4..7 lo
            uint32_t so = sb + st * 32768u + (rg ? 16384u : 0u) + SWZ(row * 128 + c16 * 16);
            const bf16* gp = rg == 0
                ? ((c16 < 4 ? Ahi : Alo) + (size_t)(nbase + row) * DD + kbase + ic * 32 + (c16 & 3) * 8)
                : ((c16 < 4 ? Bh  : Bl ) + (size_t)(obase + row) * DD + kbase + ic * 32 + (c16 & 3) * 8);
            cp_async16(so, gp);
        }
        cp_commit();
    };

    prefetch(0, 0);
    prefetch(1, 1);
    for (int ic = 0; ic < 12; ic++) {
        if (ic < 11) cp_wait<1>(); else cp_wait<0>();
        __syncthreads();
        if (ic + 2 < 12) prefetch(ic + 2, (ic + 2) % 3);

        const uint32_t sA = sb + (ic % 3) * 32768u;
        const uint32_t sB = sA + 16384u;
        #pragma unroll
        for (int k16 = 0; k16 < 2; k16++) {
            uint32_t ah[4][4], al[4][4];
            #pragma unroll
            for (int mt = 0; mt < 4; mt++) {
                int row = wm * 64 + mt * 16 + (lane & 15);
                int ch  = k16 * 2 + (lane >> 4);
                ldsm_x4(ah[mt], sA + SWZ(row * 128 + ch * 16));
                ldsm_x4(al[mt], sA + SWZ(row * 128 + (ch + 4) * 16));
            }
            #pragma unroll
            for (int ntp = 0; ntp < 4; ntp++) {
                uint32_t bh4[4], bl4[4];
                int row = wn * 64 + (ntp * 2 + (lane >> 4)) * 8 + (lane & 7);
                int ch  = k16 * 2 + ((lane >> 3) & 1);
                ldsm_x4(bh4, sB + SWZ(row * 128 + ch * 16));
                ldsm_x4(bl4, sB + SWZ(row * 128 + (ch + 4) * 16));
                #pragma unroll
                for (int mt = 0; mt < 4; mt++) {
                    mma_bf(acc[mt][2*ntp],   ah[mt], bh4 + 0);
                    mma_bf(acc[mt][2*ntp+1], ah[mt], bh4 + 2);
                    mma_bf(acc[mt][2*ntp],   ah[mt], bl4 + 0);
                    mma_bf(acc[mt][2*ntp+1], ah[mt], bl4 + 2);
                    mma_bf(acc[mt][2*ntp],   al[mt], bh4 + 0);
                    mma_bf(acc[mt][2*ntp+1], al[mt], bh4 + 2);
                }
            }
        }
    }

    if (blockIdx.z == 0) {
        #pragma unroll
        for (int nt = 0; nt < 8; nt++) {
            const int col = obase + wn * 64 + nt * 8 + 2 * (lane & 3);
            const float2 bs = *(const float2*)(bias + col);
            #pragma unroll
            for (int mt = 0; mt < 4; mt++) {
                const int r0 = nbase + wm * 64 + mt * 16 + (lane >> 2);
                #pragma unroll
                for (int half = 0; half < 2; half++) {
                    const int r = r0 + half * 8;
                    const size_t idx = (size_t)r * DD + col;
                    const float2 rr = *(const float2*)(res + idx);
                    float2 o;
                    o.x = acc[mt][nt][2*half]   + bs.x + rr.x;
                    o.y = acc[mt][nt][2*half+1] + bs.y + rr.y;
                    *(float2*)(Of0 + idx) = o;
                }
            }
        }
    } else {
        #pragma unroll
        for (int nt = 0; nt < 8; nt++) {
            const int col = obase + wn * 64 + nt * 8 + 2 * (lane & 3);
            #pragma unroll
            for (int mt = 0; mt < 4; mt++) {
                const int r0 = nbase + wm * 64 + mt * 16 + (lane >> 2);
                #pragma unroll
                for (int half = 0; half < 2; half++) {
                    const int r = r0 + half * 8;
                    const size_t idx = (size_t)r * DD + col;
                    float2 o;
                    o.x = acc[mt][nt][2*half];
                    o.y = acc[mt][nt][2*half+1];
                    *(float2*)(Of1 + idx) = o;
                }
            }
        }
    }
}

// ---------------------------------------------------------------------------
// Flash attention (R7/R9 config — best measured), 3xBF16 HMMA, no-max softmax.
// 64-query CTAs: grid (32, 48), 128 thr (4 warps x 16 q-rows), 32-key tiles.
// 3-stage in-place pipeline in 48KB, ONE __syncthreads per tile, 4 CTAs/SM.
// ---------------------------------------------------------------------------
__global__ __launch_bounds__(128, 4)
void attn_mma(const bf16* __restrict__ Qhi, const bf16* __restrict__ Qlo,
              const bf16* __restrict__ Khi, const bf16* __restrict__ Klo,
              const bf16* __restrict__ Vhi, const bf16* __restrict__ Vlo,
              bf16* __restrict__ Chi, bf16* __restrict__ Clo)
{
    extern __shared__ char smem[];
    const uint32_t sb = smem_to_u32(smem);
    const int t = threadIdx.x, lane = t & 31, wid = t >> 5;
    const int bh = blockIdx.y, q0 = blockIdx.x * 64;
    const size_t bhoff = (size_t)bh * SEQ * HDIM;

    // Q tile (64 rows) -> stage-2 region (sb+32KB): hi at +0, lo at +8KB
    #pragma unroll
    for (int q = 0; q < 8; q++) {
        int idx = t + 128 * q;                 // 0..1023
        int rg = idx >> 9;                     // 0 hi, 1 lo
        int row = (idx >> 3) & 63;
        int c16 = idx & 7;
        uint32_t so = sb + 32768u + rg * 8192u + SWZ(row * 128 + c16 * 16);
        const bf16* gp = (rg ? Qlo : Qhi) + bhoff + (size_t)(q0 + row) * HDIM + c16 * 8;
        cp_async16(so, gp);
    }
    cp_commit();

    // KV stage (32 keys): KH 4KB | KL 4KB | VH 4KB | VL 4KB = 16KB at st*16KB
    auto prefetch_kv = [&](int kt, int st) {
        #pragma unroll
        for (int q = 0; q < 8; q++) {
            int idx = t + 128 * q;             // 0..1023
            int rg  = idx >> 8;                // 0 KH, 1 KL, 2 VH, 3 VL
            int row = (idx >> 3) & 31;
            int c16 = idx & 7;
            uint32_t so = sb + st * 16384u + rg * 4096u + SWZ(row * 128 + c16 * 16);
            const bf16* base = rg == 0 ? Khi : (rg == 1 ? Klo : (rg == 2 ? Vhi : Vlo));
            cp_async16(so, base + bhoff + (size_t)(kt * 32 + row) * HDIM + c16 * 8);
        }
        cp_commit();
    };

    prefetch_kv(0, 0);
    prefetch_kv(1, 1);
    cp_wait<1>();        // Q + kv0 done (kv1 may still be in flight)
    __syncthreads();

    // Q fragments (persistent) from stage-2 region
    uint32_t qh[4][4], ql[4][4];
    #pragma unroll
    for (int k16 = 0; k16 < 4; k16++) {
        int row = wid * 16 + (lane & 15);
        int ch  = k16 * 2 + (lane >> 4);
        ldsm_x4(qh[k16], sb + 32768u + SWZ(row * 128 + ch * 16));
        ldsm_x4(ql[k16], sb + 32768u + 8192u + SWZ(row * 128 + ch * 16));
    }
    __syncthreads();     // all warps done reading Q before stage 2 is reused

    float oacc[8][4];
    #pragma unroll
    for (int i = 0; i < 8; i++)
        #pragma unroll
        for (int j = 0; j < 4; j++) oacc[i][j] = 0.0f;
    float lsum0 = 0.0f, lsum1 = 0.0f;

    for (int kt = 0; kt < 64; kt++) {
        if (kt > 0) {
            if (kt < 63) cp_wait<1>(); else cp_wait<0>();
            __syncthreads();   // stage kt ready; stage kt-1 fully consumed
        }
        if (kt + 2 < 64) prefetch_kv(kt + 2, (kt + 2) % 3);

        const uint32_t sKH = sb + (uint32_t)(kt % 3) * 16384u;
        const uint32_t sKL = sKH + 4096u;
        const uint32_t sVH = sKH + 8192u;
        const uint32_t sVL = sKH + 12288u;

        // S = Q·K^T over 32 keys (2 ntp x 2 n8)
        float sacc[4][4];
        #pragma unroll
        for (int i = 0; i < 4; i++)
            #pragma unroll
            for (int j = 0; j < 4; j++) sacc[i][j] = 0.0f;

        #pragma unroll
        for (int ntp = 0; ntp < 2; ntp++) {
            #pragma unroll
            for (int k16 = 0; k16 < 4; k16++) {
                uint32_t kh4[4], kl4[4];
                int row = (ntp * 2 + (lane >> 4)) * 8 + (lane & 7);
                int ch  = k16 * 2 + ((lane >> 3) & 1);
                ldsm_x4(kh4, sKH + SWZ(row * 128 + ch * 16));
                ldsm_x4(kl4, sKL + SWZ(row * 128 + ch * 16));
                mma_bf(sacc[2*ntp],   qh[k16], kh4 + 0);
                mma_bf(sacc[2*ntp],   qh[k16], kl4 + 0);
                mma_bf(sacc[2*ntp],   ql[k16], kh4 + 0);
                mma_bf(sacc[2*ntp+1], qh[k16], kh4 + 2);
                mma_bf(sacc[2*ntp+1], qh[k16], kl4 + 2);
                mma_bf(sacc[2*ntp+1], ql[k16], kh4 + 2);
            }
        }

        // exp (no shift) + pack P as A-fragments (hi/lo)
        uint32_t ph[2][4], pl[2][4];
        #pragma unroll
        for (int pp = 0; pp < 2; pp++) {
            float e[8];
            #pragma unroll
            for (int j = 0; j < 4; j++) {
                e[j]     = __expf(sacc[2*pp][j]);
                e[4 + j] = __expf(sacc[2*pp+1][j]);
            }
            lsum0 += (e[0] + e[1]) + (e[4] + e[5]);
            lsum1 += (e[2] + e[3]) + (e[6] + e[7]);
            split2(e[0], e[1], ph[pp][0], pl[pp][0]);
            split2(e[2], e[3], ph[pp][1], pl[pp][1]);
            split2(e[4], e[5], ph[pp][2], pl[pp][2]);
            split2(e[6], e[7], ph[pp][3], pl[pp][3]);
        }

        // O += P·V
        #pragma unroll
        for (int pp = 0; pp < 2; pp++) {
            const int kk0 = pp * 16;
            #pragma unroll
            for (int dtp = 0; dtp < 4; dtp++) {
                uint32_t vh4[4], vl4[4];
                int row = kk0 + (lane & 15);
                int ch  = dtp * 2 + (lane >> 4);
                ldsm_x4_t(vh4, sVH + SWZ(row * 128 + ch * 16));
                ldsm_x4_t(vl4, sVL + SWZ(row * 128 + ch * 16));
                mma_bf(oacc[2*dtp],   ph[pp], vh4 + 0);
                mma_bf(oacc[2*dtp],   ph[pp], vl4 + 0);
                mma_bf(oacc[2*dtp],   pl[pp], vh4 + 0);
                mma_bf(oacc[2*dtp+1], ph[pp], vh4 + 2);
                mma_bf(oacc[2*dtp+1], ph[pp], vl4 + 2);
                mma_bf(oacc[2*dtp+1], pl[pp], vh4 + 2);
            }
        }
    }

    // Row sums across the quad, then normalize + store
    lsum0 += __shfl_xor_sync(0xffffffffu, lsum0, 1);
    lsum0 += __shfl_xor_sync(0xffffffffu, lsum0, 2);
    lsum1 += __shfl_xor_sync(0xffffffffu, lsum1, 1);
    lsum1 += __shfl_xor_sync(0xffffffffu, lsum1, 2);
    const float inv0 = 1.0f / lsum0, inv1 = 1.0f / lsum1;
    const int bb = bh / NH, hh = bh % NH;
    const int r0 = q0 + wid * 16 + (lane >> 2);
    #pragma unroll
    for (int dt = 0; dt < 8; dt++) {
        const int col = hh * 64 + dt * 8 + 2 * (lane & 3);
        const size_t i0 = ((size_t)(bb * SEQ) + r0) * DD + col;
        const size_t i1 = i0 + (size_t)8 * DD;
        uint32_t H, L;
        split2(oacc[dt][0] * inv0, oacc[dt][1] * inv0, H, L);
        *(uint32_t*)(Chi + i0) = H; *(uint32_t*)(Clo + i0) = L;
        split2(oacc[dt][2] * inv1, oacc[dt][3] * inv1, H, L);
        *(uint32_t*)(Chi + i1) = H; *(uint32_t*)(Clo + i1) = L;
    }
}

// ---------------------------------------------------------------------------
// LayerNorm (custom): sums split-K partials, then mean, unbiased std (ddof=1),
// (x-mean)/(std+eps)
// ---------------------------------------------------------------------------
__global__ __launch_bounds__(192)
void ln_kernel(const float* __restrict__ Hin0, const float* __restrict__ Hin1,
               float* __restrict__ out)
{
    __shared__ float red[6];
    const int rowb = blockIdx.x;
    const int t = threadIdx.x;
    const float4 a = *(const float4*)(Hin0 + (size_t)rowb * DD + t * 4);
    const float4 b = *(const float4*)(Hin1 + (size_t)rowb * DD + t * 4);
    float4 v;
    v.x = a.x + b.x; v.y = a.y + b.y; v.z = a.z + b.z; v.w = a.w + b.w;

    float s = (v.x + v.y) + (v.z + v.w);
    #pragma unroll
    for (int off = 16; off >= 1; off >>= 1) s += __shfl_xor_sync(0xffffffffu, s, off);
    if ((t & 31) == 0) red[t >> 5] = s;
    __syncthreads();
    float tot = (red[0] + red[1]) + (red[2] + red[3]) + (red[4] + red[5]);
    const float mean = tot * (1.0f / 768.0f);

    float d0 = v.x - mean, d1 = v.y - mean, d2 = v.z - mean, d3 = v.w - mean;
    float sq = (d0 * d0 + d1 * d1) + (d2 * d2 + d3 * d3);
    #pragma unroll
    for (int off = 16; off >= 1; off >>= 1) sq += __shfl_xor_sync(0xffffffffu, sq, off);
    __syncthreads();
    if ((t & 31) == 0) red[t >> 5] = sq;
    __syncthreads();
    float ssq = (red[0] + red[1]) + (red[2] + red[3]) + (red[4] + red[5]);

    const float var = ssq * (1.0f / 767.0f);
    const float inv = 1.0f / (sqrtf(var) + 1e-12f);

    float4 o;
    o.x = d0 * inv; o.y = d1 * inv; o.z = d2 * inv; o.w = d3 * inv;
    *(float4*)(out + (size_t)rowb * DD + t * 4) = o;
}

// ---------------------------------------------------------------------------
// Launch
// ---------------------------------------------------------------------------
extern "C" void kernel_launch(void* const* d_in, const int* in_sizes, int n_in,
                              void* d_out, int out_size)
{
    const float* h  = (const float*)d_in[0];
    const float* Wq = (const float*)d_in[1];
    const float* bq = (const float*)d_in[2];
    const float* Wk = (const float*)d_in[3];
    const float* bk = (const float*)d_in[4];
    const float* Wv = (const float*)d_in[5];
    const float* bv = (const float*)d_in[6];
    const float* Wo = (const float*)d_in[7];
    const float* bo = (const float*)d_in[8];

    bf16 *hhi, *hlo, *wqh, *wql, *wkh, *wkl, *wvh, *wvl, *woh, *wol;
    bf16 *qhi, *qlo, *khi, *klo, *vhi, *vlo, *chi, *clo;
    float *hp, *hp2;
    cudaGetSymbolAddress((void**)&hhi, g_hhi);  cudaGetSymbolAddress((void**)&hlo, g_hlo);
    cudaGetSymbolAddress((void**)&wqh, g_Wqhi); cudaGetSymbolAddress((void**)&wql, g_Wqlo);
    cudaGetSymbolAddress((void**)&wkh, g_Wkhi); cudaGetSymbolAddress((void**)&wkl, g_Wklo);
    cudaGetSymbolAddress((void**)&wvh, g_Wvhi); cudaGetSymbolAddress((void**)&wvl, g_Wvlo);
    cudaGetSymbolAddress((void**)&woh, g_Wohi); cudaGetSymbolAddress((void**)&wol, g_Wolo);
    cudaGetSymbolAddress((void**)&qhi, g_Qhi);  cudaGetSymbolAddress((void**)&qlo, g_Qlo);
    cudaGetSymbolAddress((void**)&khi, g_Khi);  cudaGetSymbolAddress((void**)&klo, g_Klo);
    cudaGetSymbolAddress((void**)&vhi, g_Vhi);  cudaGetSymbolAddress((void**)&vlo, g_Vlo);
    cudaGetSymbolAddress((void**)&chi, g_Chi);  cudaGetSymbolAddress((void**)&clo, g_Clo);
    cudaGetSymbolAddress((void**)&hp,  g_h);
    cudaGetSymbolAddress((void**)&hp2, g_h2);

    cudaFuncSetAttribute(gemm_qkv,     cudaFuncAttributeMaxDynamicSharedMemorySize, 98304);
    cudaFuncSetAttribute(gemm_o_split, cudaFuncAttributeMaxDynamicSharedMemorySize, 98304);
    cudaFuncSetAttribute(attn_mma,     cudaFuncAttributeMaxDynamicSharedMemorySize, 49152);

    // Fused hi/lo splits: hidden + 4 weights in one launch
    split_all<<<(N4TOT + 255) / 256, 256>>>(
        (const float4*)h,
        (const float4*)Wq, (const float4*)Wk, (const float4*)Wv, (const float4*)Wo,
        (uint32_t*)hhi, (uint32_t*)hlo,
        (uint32_t*)wqh, (uint32_t*)wql, (uint32_t*)wkh, (uint32_t*)wkl,
        (uint32_t*)wvh, (uint32_t*)wvl, (uint32_t*)woh, (uint32_t*)wol);

    gemm_qkv<<<dim3(NROWS / 128, DD / 128, 3), 128, 98304>>>(
        hhi, hlo,
        wqh, wql, bq, wkh, wkl, bk, wvh, wvl, bv,
        qhi, qlo, khi, klo, vhi, vlo);

    attn_mma<<<dim3(SEQ / 64, BAT * NH), 128, 49152>>>(qhi, qlo, khi, klo, vhi, vlo, chi, clo);

    gemm_o_split<<<dim3(NROWS / 128, DD / 128, 2), 128, 98304>>>(
        chi, clo, woh, wol, bo, h, hp, hp2);

    ln_kernel<<<NROWS, 192>>>(hp, hp2, (float*)d_out);
}